// round 2
// baseline (speedup 1.0000x reference)
#include <cuda_runtime.h>
#include <cuda_bf16.h>
#include <math.h>

#define B_SZ   4
#define T_LEN  2048
#define S_LEN  4096
#define DIM    256
#define HEADS  8
#define DHEAD  32
#define HID    256            // HEADS*DHEAD
#define SCALE  0.17677669529663687f   // 32^-0.5

// ---------------- scratch (no allocation allowed) ----------------
__device__ float g_q [B_SZ * T_LEN * HID];          // 8.4 MB   [B,T,H*D]
__device__ float g_kv[B_SZ * S_LEN * 2 * HID];      // 33.6 MB  [B,S,2*H*D]
__device__ float g_ao[B_SZ * T_LEN * HID];          // 8.4 MB   [B,T,H*D]

// ---------------- tiled SGEMM: C[M,N] = A[M,K] @ W[K,N] (+bias) ----------------
// BM=BN=64, BK=16, 256 threads, 4x4 micro-tile per thread.
template<bool BIAS>
__global__ void sgemm_kernel(const float* __restrict__ A,
                             const float* __restrict__ W,
                             const float* __restrict__ bias,
                             float* __restrict__ C,
                             int M, int N, int K) {
    __shared__ float As[16][64];   // [k][m]
    __shared__ float Ws[16][64];   // [k][n]

    const int t  = threadIdx.x;
    const int tx = t & 15;          // 0..15  (n)
    const int ty = t >> 4;          // 0..15  (m)
    const int m0 = blockIdx.y * 64;
    const int n0 = blockIdx.x * 64;

    // A-tile load map: 64 rows x 16 cols, float4 along K
    const int ar = t >> 2;          // 0..63
    const int ac = (t & 3) * 4;     // 0,4,8,12
    // W-tile load map: 16 rows x 64 cols, float4 along N
    const int wr = t >> 4;          // 0..15
    const int wc = (t & 15) * 4;    // 0..60

    float acc[4][4];
    #pragma unroll
    for (int i = 0; i < 4; i++)
        #pragma unroll
        for (int j = 0; j < 4; j++) acc[i][j] = 0.f;

    for (int k0 = 0; k0 < K; k0 += 16) {
        float4 a4 = *(const float4*)&A[(size_t)(m0 + ar) * K + k0 + ac];
        As[ac + 0][ar] = a4.x;
        As[ac + 1][ar] = a4.y;
        As[ac + 2][ar] = a4.z;
        As[ac + 3][ar] = a4.w;
        *(float4*)&Ws[wr][wc] = *(const float4*)&W[(size_t)(k0 + wr) * N + n0 + wc];
        __syncthreads();

        #pragma unroll
        for (int kk = 0; kk < 16; kk++) {
            float4 av = *(const float4*)&As[kk][ty * 4];
            float4 wv = *(const float4*)&Ws[kk][tx * 4];
            float a[4] = {av.x, av.y, av.z, av.w};
            float w[4] = {wv.x, wv.y, wv.z, wv.w};
            #pragma unroll
            for (int i = 0; i < 4; i++)
                #pragma unroll
                for (int j = 0; j < 4; j++)
                    acc[i][j] += a[i] * w[j];
        }
        __syncthreads();
    }

    #pragma unroll
    for (int i = 0; i < 4; i++) {
        const size_t row = (size_t)(m0 + ty * 4 + i) * N + n0 + tx * 4;
        #pragma unroll
        for (int j = 0; j < 4; j++) {
            float v = acc[i][j];
            if (BIAS) v += bias[n0 + tx * 4 + j];
            C[row + j] = v;
        }
    }
}

// ---------------- flash attention (fp32, online softmax) ----------------
// grid: (T/16, H, B). block: 256 threads (8 warps, 2 q-rows each).
// K tile stored transposed [d][s] (stride 33), V tile [s][d] (stride 33).
__global__ void attn_kernel(const float* __restrict__ q,
                            const float* __restrict__ kv,
                            float* __restrict__ ao) {
    __shared__ float Ksh[32 * 33];   // [d][s]
    __shared__ float Vsh[32 * 33];   // [s][d]
    __shared__ float Qsh[16 * 32];   // [r][d], pre-scaled

    const int b = blockIdx.z;
    const int h = blockIdx.y;
    const int t_base = blockIdx.x * 16;
    const int tid  = threadIdx.x;
    const int warp = tid >> 5;
    const int lane = tid & 31;

    // load & pre-scale Q rows
    for (int i = tid; i < 16 * 32; i += 256) {
        int r = i >> 5, d = i & 31;
        Qsh[i] = q[((size_t)(b * T_LEN + t_base + r)) * HID + h * DHEAD + d] * SCALE;
    }
    __syncthreads();

    const int r0 = warp * 2, r1 = warp * 2 + 1;
    float m0 = -1e30f, m1 = -1e30f;
    float l0 = 0.f,    l1 = 0.f;
    float o0 = 0.f,    o1 = 0.f;      // lane owns output dim d = lane

    const float* kvbase = kv + ((size_t)b * S_LEN) * (2 * HID) + h * DHEAD;
    const int lr = tid >> 3;          // 0..31  (s row)
    const int lc = (tid & 7) * 4;     // 0..28  (d col base)

    for (int s0 = 0; s0 < S_LEN; s0 += 32) {
        // cooperative load of K/V chunk
        const float* src = kvbase + (size_t)(s0 + lr) * (2 * HID) + lc;
        float4 k4 = *(const float4*)(src);
        float4 v4 = *(const float4*)(src + HID);
        Ksh[(lc + 0) * 33 + lr] = k4.x;   // transposed store (conflict-free)
        Ksh[(lc + 1) * 33 + lr] = k4.y;
        Ksh[(lc + 2) * 33 + lr] = k4.z;
        Ksh[(lc + 3) * 33 + lr] = k4.w;
        Vsh[lr * 33 + lc + 0] = v4.x;
        Vsh[lr * 33 + lc + 1] = v4.y;
        Vsh[lr * 33 + lc + 2] = v4.z;
        Vsh[lr * 33 + lc + 3] = v4.w;
        __syncthreads();

        // ---- scores: lane handles s = lane; cache K column in registers
        float kr[32];
        #pragma unroll
        for (int d = 0; d < 32; d++) kr[d] = Ksh[d * 33 + lane];

        float sc0 = 0.f, sc1 = 0.f;
        #pragma unroll
        for (int i = 0; i < 8; i++) {
            float4 q0 = *(const float4*)&Qsh[r0 * 32 + i * 4];
            float4 q1 = *(const float4*)&Qsh[r1 * 32 + i * 4];
            sc0 += q0.x * kr[i*4+0] + q0.y * kr[i*4+1] + q0.z * kr[i*4+2] + q0.w * kr[i*4+3];
            sc1 += q1.x * kr[i*4+0] + q1.y * kr[i*4+1] + q1.z * kr[i*4+2] + q1.w * kr[i*4+3];
        }

        // ---- online softmax (row 0)
        float mc = sc0;
        #pragma unroll
        for (int off = 16; off; off >>= 1)
            mc = fmaxf(mc, __shfl_xor_sync(0xffffffffu, mc, off));
        float mn0 = fmaxf(m0, mc);
        float p0  = __expf(sc0 - mn0);
        float ls0 = p0;
        #pragma unroll
        for (int off = 16; off; off >>= 1)
            ls0 += __shfl_xor_sync(0xffffffffu, ls0, off);
        float c0 = __expf(m0 - mn0);
        l0 = l0 * c0 + ls0;
        o0 *= c0;
        m0 = mn0;

        // ---- online softmax (row 1)
        mc = sc1;
        #pragma unroll
        for (int off = 16; off; off >>= 1)
            mc = fmaxf(mc, __shfl_xor_sync(0xffffffffu, mc, off));
        float mn1 = fmaxf(m1, mc);
        float p1  = __expf(sc1 - mn1);
        float ls1 = p1;
        #pragma unroll
        for (int off = 16; off; off >>= 1)
            ls1 += __shfl_xor_sync(0xffffffffu, ls1, off);
        float c1 = __expf(m1 - mn1);
        l1 = l1 * c1 + ls1;
        o1 *= c1;
        m1 = mn1;

        // ---- P @ V : broadcast p from lane s, lane accumulates dim d=lane
        #pragma unroll
        for (int s = 0; s < 32; s++) {
            float vv  = Vsh[s * 33 + lane];
            float ps0 = __shfl_sync(0xffffffffu, p0, s);
            float ps1 = __shfl_sync(0xffffffffu, p1, s);
            o0 += ps0 * vv;
            o1 += ps1 * vv;
        }
        __syncthreads();
    }

    ao[((size_t)(b * T_LEN + t_base + r0)) * HID + h * DHEAD + lane] = o0 / l0;
    ao[((size_t)(b * T_LEN + t_base + r1)) * HID + h * DHEAD + lane] = o1 / l1;
}

// ---------------- launch ----------------
extern "C" void kernel_launch(void* const* d_in, const int* in_sizes, int n_in,
                              void* d_out, int out_size) {
    const float* x    = (const float*)d_in[0];   // [B,T,256]
    const float* ctx  = (const float*)d_in[1];   // [B,S,256]
    const float* w_q  = (const float*)d_in[2];   // [256,256]
    const float* w_kv = (const float*)d_in[3];   // [256,512]
    const float* w_o  = (const float*)d_in[4];   // [256,256]
    const float* b_o  = (const float*)d_in[5];   // [256]
    float* out = (float*)d_out;                  // [B,T,256]

    float* q  = nullptr; cudaGetSymbolAddress((void**)&q,  g_q);
    float* kv = nullptr; cudaGetSymbolAddress((void**)&kv, g_kv);
    float* ao = nullptr; cudaGetSymbolAddress((void**)&ao, g_ao);

    const int MQ = B_SZ * T_LEN;   // 8192
    const int MK = B_SZ * S_LEN;   // 16384

    // Q = x @ w_q
    sgemm_kernel<false><<<dim3(HID / 64, MQ / 64), 256>>>(x, w_q, nullptr, q, MQ, HID, DIM);
    // KV = ctx @ w_kv
    sgemm_kernel<false><<<dim3(2 * HID / 64, MK / 64), 256>>>(ctx, w_kv, nullptr, kv, MK, 2 * HID, DIM);
    // attention
    attn_kernel<<<dim3(T_LEN / 16, HEADS, B_SZ), 256>>>(q, kv, ao);
    // out = ao @ w_out + b_out
    sgemm_kernel<true><<<dim3(DIM / 64, MQ / 64), 256>>>(ao, w_o, b_o, out, MQ, DIM, HID);
}

// round 3
// speedup vs baseline: 3.3466x; 3.3466x over previous
#include <cuda_runtime.h>
#include <cuda_bf16.h>
#include <math.h>

#define B_SZ   4
#define T_LEN  2048
#define S_LEN  4096
#define DIM    256
#define HEADS  8
#define DHEAD  32
#define HID    256
#define SCALE  0.17677669529663687f   // 32^-0.5

// ---------------- scratch (no allocation allowed) ----------------
__device__ float g_q [B_SZ * T_LEN * HID];
__device__ float g_kv[B_SZ * S_LEN * 2 * HID];
__device__ float g_ao[B_SZ * T_LEN * HID];

// ---------------- helpers ----------------
__device__ __forceinline__ float tf32r(float x) {
    unsigned int u;
    asm("cvt.rna.tf32.f32 %0, %1;" : "=r"(u) : "f"(x));
    return __uint_as_float(u);
}

__device__ __forceinline__ void mma_tf32(float* c,
                                         unsigned a0, unsigned a1, unsigned a2, unsigned a3,
                                         unsigned b0, unsigned b1) {
    asm volatile(
        "mma.sync.aligned.m16n8k8.row.col.f32.tf32.tf32.f32 "
        "{%0,%1,%2,%3}, {%4,%5,%6,%7}, {%8,%9}, {%0,%1,%2,%3};"
        : "+f"(c[0]), "+f"(c[1]), "+f"(c[2]), "+f"(c[3])
        : "r"(a0), "r"(a1), "r"(a2), "r"(a3), "r"(b0), "r"(b1));
}

// ---------------- tiled SGEMM (projections, fp32) ----------------
template<bool BIAS>
__global__ void sgemm_kernel(const float* __restrict__ A,
                             const float* __restrict__ W,
                             const float* __restrict__ bias,
                             float* __restrict__ C,
                             int M, int N, int K) {
    __shared__ float As[16][64];
    __shared__ float Ws[16][64];

    const int t  = threadIdx.x;
    const int tx = t & 15;
    const int ty = t >> 4;
    const int m0 = blockIdx.y * 64;
    const int n0 = blockIdx.x * 64;

    const int ar = t >> 2;
    const int ac = (t & 3) * 4;
    const int wr = t >> 4;
    const int wc = (t & 15) * 4;

    float acc[4][4];
    #pragma unroll
    for (int i = 0; i < 4; i++)
        #pragma unroll
        for (int j = 0; j < 4; j++) acc[i][j] = 0.f;

    for (int k0 = 0; k0 < K; k0 += 16) {
        float4 a4 = *(const float4*)&A[(size_t)(m0 + ar) * K + k0 + ac];
        As[ac + 0][ar] = a4.x;
        As[ac + 1][ar] = a4.y;
        As[ac + 2][ar] = a4.z;
        As[ac + 3][ar] = a4.w;
        *(float4*)&Ws[wr][wc] = *(const float4*)&W[(size_t)(k0 + wr) * N + n0 + wc];
        __syncthreads();

        #pragma unroll
        for (int kk = 0; kk < 16; kk++) {
            float4 av = *(const float4*)&As[kk][ty * 4];
            float4 wv = *(const float4*)&Ws[kk][tx * 4];
            float a[4] = {av.x, av.y, av.z, av.w};
            float w[4] = {wv.x, wv.y, wv.z, wv.w};
            #pragma unroll
            for (int i = 0; i < 4; i++)
                #pragma unroll
                for (int j = 0; j < 4; j++)
                    acc[i][j] += a[i] * w[j];
        }
        __syncthreads();
    }

    #pragma unroll
    for (int i = 0; i < 4; i++) {
        const size_t row = (size_t)(m0 + ty * 4 + i) * N + n0 + tx * 4;
        #pragma unroll
        for (int j = 0; j < 4; j++) {
            float v = acc[i][j];
            if (BIAS) v += bias[n0 + tx * 4 + j];
            C[row + j] = v;
        }
    }
}

// ---------------- tensor-core flash attention (tf32, split-QK) ----------------
// grid (T/64, H, B), block 128 (4 warps, 16 q-rows each). BN=64 per chunk.
#define QS 36   // Q smem stride
#define KS 36   // K smem stride
#define VS 40   // V smem stride
#define PS 68   // P smem stride

__global__ void attn_tc_kernel(const float* __restrict__ q,
                               const float* __restrict__ kv,
                               float* __restrict__ ao) {
    extern __shared__ float sm[];
    float* Qhi = sm;                    // 64*36
    float* Qlo = Qhi + 64 * QS;         // 64*36
    float* Khi = Qlo + 64 * QS;         // 64*36
    float* Klo = Khi + 64 * KS;         // 64*36
    float* Vsh = Klo + 64 * KS;         // 64*40
    float* Psh = Vsh + 64 * VS;         // 64*68

    const int b    = blockIdx.z;
    const int h    = blockIdx.y;
    const int t0   = blockIdx.x * 64;
    const int tid  = threadIdx.x;
    const int warp = tid >> 5;
    const int lane = tid & 31;
    const int g    = lane >> 2;         // groupID 0..7
    const int qd   = lane & 3;          // threadID-in-group 0..3

    // load + scale + split Q tile [64 x 32]
    for (int i = tid; i < 64 * 32; i += 128) {
        int r = i >> 5, c = i & 31;
        float x  = q[((size_t)(b * T_LEN + t0 + r)) * HID + h * DHEAD + c] * SCALE;
        float hi = tf32r(x);
        Qhi[r * QS + c] = hi;
        Qlo[r * QS + c] = tf32r(x - hi);
    }

    float m0 = -1e30f, m1 = -1e30f;
    float l0 = 0.f,    l1 = 0.f;
    float O[4][4];
    #pragma unroll
    for (int j = 0; j < 4; j++)
        #pragma unroll
        for (int i = 0; i < 4; i++) O[j][i] = 0.f;

    const float* kvbase = kv + ((size_t)b * S_LEN) * (2 * HID) + h * DHEAD;
    const int prow = warp * 16 + g;

    for (int s0 = 0; s0 < S_LEN; s0 += 64) {
        __syncthreads();   // prior chunk's K/V reads + P reads done before overwrite
        // load K (split) and V (tf32) chunk [64 x 32]
        for (int i = tid; i < 64 * 32; i += 128) {
            int r = i >> 5, c = i & 31;
            const float* src = kvbase + (size_t)(s0 + r) * (2 * HID) + c;
            float kx = src[0];
            float kh = tf32r(kx);
            Khi[r * KS + c] = kh;
            Klo[r * KS + c] = tf32r(kx - kh);
            Vsh[r * VS + c] = tf32r(src[HID]);
        }
        __syncthreads();

        // ---- S = Q @ K^T  (64x64 per block, 16x64 per warp), 3-term tf32 split
        float sacc[8][4];
        #pragma unroll
        for (int j = 0; j < 8; j++)
            #pragma unroll
            for (int i = 0; i < 4; i++) sacc[j][i] = 0.f;

        #pragma unroll
        for (int k = 0; k < 4; k++) {
            const int kc = k * 8;
            unsigned ah0 = __float_as_uint(Qhi[(prow    ) * QS + kc + qd    ]);
            unsigned ah1 = __float_as_uint(Qhi[(prow + 8) * QS + kc + qd    ]);
            unsigned ah2 = __float_as_uint(Qhi[(prow    ) * QS + kc + qd + 4]);
            unsigned ah3 = __float_as_uint(Qhi[(prow + 8) * QS + kc + qd + 4]);
            unsigned al0 = __float_as_uint(Qlo[(prow    ) * QS + kc + qd    ]);
            unsigned al1 = __float_as_uint(Qlo[(prow + 8) * QS + kc + qd    ]);
            unsigned al2 = __float_as_uint(Qlo[(prow    ) * QS + kc + qd + 4]);
            unsigned al3 = __float_as_uint(Qlo[(prow + 8) * QS + kc + qd + 4]);
            #pragma unroll
            for (int j = 0; j < 8; j++) {
                const int nr = j * 8 + g;
                unsigned bh0 = __float_as_uint(Khi[nr * KS + kc + qd    ]);
                unsigned bh1 = __float_as_uint(Khi[nr * KS + kc + qd + 4]);
                unsigned bl0 = __float_as_uint(Klo[nr * KS + kc + qd    ]);
                unsigned bl1 = __float_as_uint(Klo[nr * KS + kc + qd + 4]);
                mma_tf32(sacc[j], ah0, ah1, ah2, ah3, bh0, bh1);
                mma_tf32(sacc[j], ah0, ah1, ah2, ah3, bl0, bl1);
                mma_tf32(sacc[j], al0, al1, al2, al3, bh0, bh1);
            }
        }

        // ---- online softmax on register fragments (rows prow, prow+8)
        float mx0 = -1e30f, mx1 = -1e30f;
        #pragma unroll
        for (int j = 0; j < 8; j++) {
            mx0 = fmaxf(mx0, fmaxf(sacc[j][0], sacc[j][1]));
            mx1 = fmaxf(mx1, fmaxf(sacc[j][2], sacc[j][3]));
        }
        #pragma unroll
        for (int off = 1; off < 4; off <<= 1) {
            mx0 = fmaxf(mx0, __shfl_xor_sync(0xffffffffu, mx0, off));
            mx1 = fmaxf(mx1, __shfl_xor_sync(0xffffffffu, mx1, off));
        }
        const float mn0 = fmaxf(m0, mx0);
        const float mn1 = fmaxf(m1, mx1);
        const float c0  = __expf(m0 - mn0);
        const float c1  = __expf(m1 - mn1);
        m0 = mn0; m1 = mn1;

        float ls0 = 0.f, ls1 = 0.f;
        #pragma unroll
        for (int j = 0; j < 8; j++) {
            sacc[j][0] = __expf(sacc[j][0] - mn0);
            sacc[j][1] = __expf(sacc[j][1] - mn0);
            sacc[j][2] = __expf(sacc[j][2] - mn1);
            sacc[j][3] = __expf(sacc[j][3] - mn1);
            ls0 += sacc[j][0] + sacc[j][1];
            ls1 += sacc[j][2] + sacc[j][3];
        }
        #pragma unroll
        for (int off = 1; off < 4; off <<= 1) {
            ls0 += __shfl_xor_sync(0xffffffffu, ls0, off);
            ls1 += __shfl_xor_sync(0xffffffffu, ls1, off);
        }
        l0 = l0 * c0 + ls0;
        l1 = l1 * c1 + ls1;
        #pragma unroll
        for (int j = 0; j < 4; j++) {
            O[j][0] *= c0; O[j][1] *= c0;
            O[j][2] *= c1; O[j][3] *= c1;
        }

        // ---- stage P (tf32-rounded) into per-warp smem slice
        #pragma unroll
        for (int j = 0; j < 8; j++) {
            float2 p01 = make_float2(tf32r(sacc[j][0]), tf32r(sacc[j][1]));
            float2 p23 = make_float2(tf32r(sacc[j][2]), tf32r(sacc[j][3]));
            *(float2*)&Psh[(prow    ) * PS + j * 8 + 2 * qd] = p01;
            *(float2*)&Psh[(prow + 8) * PS + j * 8 + 2 * qd] = p23;
        }
        __syncwarp();

        // ---- O += P @ V   (16x64 @ 64x32 per warp)
        #pragma unroll
        for (int kk = 0; kk < 8; kk++) {
            const int kc = kk * 8;
            unsigned a0 = __float_as_uint(Psh[(prow    ) * PS + kc + qd    ]);
            unsigned a1 = __float_as_uint(Psh[(prow + 8) * PS + kc + qd    ]);
            unsigned a2 = __float_as_uint(Psh[(prow    ) * PS + kc + qd + 4]);
            unsigned a3 = __float_as_uint(Psh[(prow + 8) * PS + kc + qd + 4]);
            #pragma unroll
            for (int j = 0; j < 4; j++) {
                unsigned b0 = __float_as_uint(Vsh[(kc + qd    ) * VS + j * 8 + g]);
                unsigned b1 = __float_as_uint(Vsh[(kc + qd + 4) * VS + j * 8 + g]);
                mma_tf32(O[j], a0, a1, a2, a3, b0, b1);
            }
        }
    }

    // ---- epilogue: normalize + store
    const float inv0 = 1.f / l0;
    const float inv1 = 1.f / l1;
    const size_t row0 = (size_t)(b * T_LEN + t0 + prow) * HID + h * DHEAD;
    const size_t row1 = row0 + (size_t)8 * HID;
    #pragma unroll
    for (int j = 0; j < 4; j++) {
        const int d0 = j * 8 + 2 * qd;
        *(float2*)&ao[row0 + d0] = make_float2(O[j][0] * inv0, O[j][1] * inv0);
        *(float2*)&ao[row1 + d0] = make_float2(O[j][2] * inv1, O[j][3] * inv1);
    }
}

// ---------------- launch ----------------
extern "C" void kernel_launch(void* const* d_in, const int* in_sizes, int n_in,
                              void* d_out, int out_size) {
    const float* x    = (const float*)d_in[0];
    const float* ctx  = (const float*)d_in[1];
    const float* w_q  = (const float*)d_in[2];
    const float* w_kv = (const float*)d_in[3];
    const float* w_o  = (const float*)d_in[4];
    const float* b_o  = (const float*)d_in[5];
    float* out = (float*)d_out;

    float* q  = nullptr; cudaGetSymbolAddress((void**)&q,  g_q);
    float* kv = nullptr; cudaGetSymbolAddress((void**)&kv, g_kv);
    float* ao = nullptr; cudaGetSymbolAddress((void**)&ao, g_ao);

    const int MQ = B_SZ * T_LEN;   // 8192
    const int MK = B_SZ * S_LEN;   // 16384

    const int attn_smem = (64 * QS * 2 + 64 * KS * 2 + 64 * VS + 64 * PS) * sizeof(float);
    cudaFuncSetAttribute(attn_tc_kernel,
                         cudaFuncAttributeMaxDynamicSharedMemorySize, attn_smem);

    sgemm_kernel<false><<<dim3(HID / 64, MQ / 64), 256>>>(x, w_q, nullptr, q, MQ, HID, DIM);
    sgemm_kernel<false><<<dim3(2 * HID / 64, MK / 64), 256>>>(ctx, w_kv, nullptr, kv, MK, 2 * HID, DIM);
    attn_tc_kernel<<<dim3(T_LEN / 64, HEADS, B_SZ), 128, attn_smem>>>(q, kv, ao);
    sgemm_kernel<true><<<dim3(DIM / 64, MQ / 64), 256>>>(ao, w_o, b_o, out, MQ, DIM, HID);
}

// round 4
// speedup vs baseline: 3.6098x; 1.0786x over previous
#include <cuda_runtime.h>
#include <cuda_bf16.h>
#include <math.h>

#define B_SZ   4
#define T_LEN  2048
#define S_LEN  4096
#define DIM    256
#define HEADS  8
#define DHEAD  32
#define HID    256
#define SCALE  0.17677669529663687f   // 32^-0.5

// ---------------- scratch (no allocation allowed) ----------------
__device__ float g_q [B_SZ * T_LEN * HID];
__device__ float g_kv[B_SZ * S_LEN * 2 * HID];
__device__ float g_ao[B_SZ * T_LEN * HID];

// ---------------- helpers ----------------
__device__ __forceinline__ float tf32r(float x) {
    unsigned int u;
    asm("cvt.rna.tf32.f32 %0, %1;" : "=r"(u) : "f"(x));
    return __uint_as_float(u);
}

__device__ __forceinline__ void mma_tf32(float* c,
                                         unsigned a0, unsigned a1, unsigned a2, unsigned a3,
                                         unsigned b0, unsigned b1) {
    asm volatile(
        "mma.sync.aligned.m16n8k8.row.col.f32.tf32.tf32.f32 "
        "{%0,%1,%2,%3}, {%4,%5,%6,%7}, {%8,%9}, {%0,%1,%2,%3};"
        : "+f"(c[0]), "+f"(c[1]), "+f"(c[2]), "+f"(c[3])
        : "r"(a0), "r"(a1), "r"(a2), "r"(a3), "r"(b0), "r"(b1));
}

// ---------------- tf32 tensor-core GEMM (projections) ----------------
// C[M,N] = A[M,K] @ W[K,N] (+bias). 2-term split on A (A exact-ish, W tf32).
// Block: 64x64 tile, BK=32, 128 threads = 4 warps in 2x2, each warp 32x32.
#define GAS 33   // A smem stride
#define GWS 33   // W smem stride (stored transposed [n][k])
template<bool BIAS>
__global__ void gemm_tc_kernel(const float* __restrict__ A,
                               const float* __restrict__ W,
                               const float* __restrict__ bias,
                               float* __restrict__ C,
                               int M, int N, int K) {
    __shared__ float Ahi[64 * GAS];
    __shared__ float Alo[64 * GAS];
    __shared__ float Wt [64 * GWS];   // [n][k]

    const int tid  = threadIdx.x;
    const int warp = tid >> 5;
    const int lane = tid & 31;
    const int g    = lane >> 2;      // 0..7
    const int qd   = lane & 3;       // 0..3
    const int m0 = blockIdx.y * 64;
    const int n0 = blockIdx.x * 64;
    const int rm = (warp & 1) * 32;  // warp row base
    const int cn = (warp >> 1) * 32; // warp col base

    float acc[2][4][4];
    #pragma unroll
    for (int mi = 0; mi < 2; mi++)
        #pragma unroll
        for (int ni = 0; ni < 4; ni++)
            #pragma unroll
            for (int i = 0; i < 4; i++) acc[mi][ni][i] = 0.f;

    for (int k0 = 0; k0 < K; k0 += 32) {
        __syncthreads();
        // A tile 64x32, split hi/lo
        for (int i = tid; i < 64 * 32; i += 128) {
            int r = i >> 5, k = i & 31;
            float a  = A[(size_t)(m0 + r) * K + k0 + k];
            float hi = tf32r(a);
            Ahi[r * GAS + k] = hi;
            Alo[r * GAS + k] = tf32r(a - hi);
        }
        // W tile 32x64 -> transposed [n][k], tf32
        for (int i = tid; i < 64 * 32; i += 128) {
            int n = i & 63, k = i >> 6;
            Wt[n * GWS + k] = tf32r(W[(size_t)(k0 + k) * N + n0 + n]);
        }
        __syncthreads();

        #pragma unroll
        for (int ks = 0; ks < 4; ks++) {
            const int kc = ks * 8;
            #pragma unroll
            for (int mi = 0; mi < 2; mi++) {
                const int r = rm + mi * 16 + g;
                unsigned ah0 = __float_as_uint(Ahi[(r    ) * GAS + kc + qd    ]);
                unsigned ah1 = __float_as_uint(Ahi[(r + 8) * GAS + kc + qd    ]);
                unsigned ah2 = __float_as_uint(Ahi[(r    ) * GAS + kc + qd + 4]);
                unsigned ah3 = __float_as_uint(Ahi[(r + 8) * GAS + kc + qd + 4]);
                unsigned al0 = __float_as_uint(Alo[(r    ) * GAS + kc + qd    ]);
                unsigned al1 = __float_as_uint(Alo[(r + 8) * GAS + kc + qd    ]);
                unsigned al2 = __float_as_uint(Alo[(r    ) * GAS + kc + qd + 4]);
                unsigned al3 = __float_as_uint(Alo[(r + 8) * GAS + kc + qd + 4]);
                #pragma unroll
                for (int ni = 0; ni < 4; ni++) {
                    const int n = cn + ni * 8 + g;
                    unsigned b0 = __float_as_uint(Wt[n * GWS + kc + qd    ]);
                    unsigned b1 = __float_as_uint(Wt[n * GWS + kc + qd + 4]);
                    mma_tf32(acc[mi][ni], ah0, ah1, ah2, ah3, b0, b1);
                    mma_tf32(acc[mi][ni], al0, al1, al2, al3, b0, b1);
                }
            }
        }
    }

    #pragma unroll
    for (int mi = 0; mi < 2; mi++) {
        const size_t r0 = (size_t)(m0 + rm + mi * 16 + g) * N;
        const size_t r1 = r0 + (size_t)8 * N;
        #pragma unroll
        for (int ni = 0; ni < 4; ni++) {
            const int col = n0 + cn + ni * 8 + 2 * qd;
            float b0v = 0.f, b1v = 0.f;
            if (BIAS) { b0v = bias[col]; b1v = bias[col + 1]; }
            *(float2*)&C[r0 + col] = make_float2(acc[mi][ni][0] + b0v, acc[mi][ni][1] + b1v);
            *(float2*)&C[r1 + col] = make_float2(acc[mi][ni][2] + b0v, acc[mi][ni][3] + b1v);
        }
    }
}

// ---------------- tensor-core flash attention (tf32, 2-term QK split) ----------------
// grid (T/64, H, B), block 128 (4 warps, 16 q-rows each). BN=64 per chunk.
#define QS 36   // Q smem stride
#define KS 36   // K smem stride
#define VS 40   // V smem stride
#define PS 68   // P smem stride

__global__ void attn_tc_kernel(const float* __restrict__ q,
                               const float* __restrict__ kv,
                               float* __restrict__ ao) {
    extern __shared__ float sm[];
    float* Qhi = sm;                    // 64*36
    float* Qlo = Qhi + 64 * QS;         // 64*36
    float* Ksh = Qlo + 64 * QS;         // 64*36 (single tf32)
    float* Vsh = Ksh + 64 * KS;         // 64*40
    float* Psh = Vsh + 64 * VS;         // 64*68

    const int b    = blockIdx.z;
    const int h    = blockIdx.y;
    const int t0   = blockIdx.x * 64;
    const int tid  = threadIdx.x;
    const int warp = tid >> 5;
    const int lane = tid & 31;
    const int g    = lane >> 2;
    const int qd   = lane & 3;

    // load + scale + split Q tile [64 x 32]
    for (int i = tid; i < 64 * 32; i += 128) {
        int r = i >> 5, c = i & 31;
        float x  = q[((size_t)(b * T_LEN + t0 + r)) * HID + h * DHEAD + c] * SCALE;
        float hi = tf32r(x);
        Qhi[r * QS + c] = hi;
        Qlo[r * QS + c] = tf32r(x - hi);
    }

    float m0 = -1e30f, m1 = -1e30f;
    float l0 = 0.f,    l1 = 0.f;
    float O[4][4];
    #pragma unroll
    for (int j = 0; j < 4; j++)
        #pragma unroll
        for (int i = 0; i < 4; i++) O[j][i] = 0.f;

    const float* kvbase = kv + ((size_t)b * S_LEN) * (2 * HID) + h * DHEAD;
    const int prow = warp * 16 + g;

    for (int s0 = 0; s0 < S_LEN; s0 += 64) {
        __syncthreads();
        // load K (tf32) and V (tf32) chunk [64 x 32]
        for (int i = tid; i < 64 * 32; i += 128) {
            int r = i >> 5, c = i & 31;
            const float* src = kvbase + (size_t)(s0 + r) * (2 * HID) + c;
            Ksh[r * KS + c] = tf32r(src[0]);
            Vsh[r * VS + c] = tf32r(src[HID]);
        }
        __syncthreads();

        // ---- S = Q @ K^T : 2 MMAs (Qhi, Qlo) x K per 8x8
        float sacc[8][4];
        #pragma unroll
        for (int j = 0; j < 8; j++)
            #pragma unroll
            for (int i = 0; i < 4; i++) sacc[j][i] = 0.f;

        #pragma unroll
        for (int k = 0; k < 4; k++) {
            const int kc = k * 8;
            unsigned ah0 = __float_as_uint(Qhi[(prow    ) * QS + kc + qd    ]);
            unsigned ah1 = __float_as_uint(Qhi[(prow + 8) * QS + kc + qd    ]);
            unsigned ah2 = __float_as_uint(Qhi[(prow    ) * QS + kc + qd + 4]);
            unsigned ah3 = __float_as_uint(Qhi[(prow + 8) * QS + kc + qd + 4]);
            unsigned al0 = __float_as_uint(Qlo[(prow    ) * QS + kc + qd    ]);
            unsigned al1 = __float_as_uint(Qlo[(prow + 8) * QS + kc + qd    ]);
            unsigned al2 = __float_as_uint(Qlo[(prow    ) * QS + kc + qd + 4]);
            unsigned al3 = __float_as_uint(Qlo[(prow + 8) * QS + kc + qd + 4]);
            #pragma unroll
            for (int j = 0; j < 8; j++) {
                const int nr = j * 8 + g;
                unsigned b0 = __float_as_uint(Ksh[nr * KS + kc + qd    ]);
                unsigned b1 = __float_as_uint(Ksh[nr * KS + kc + qd + 4]);
                mma_tf32(sacc[j], ah0, ah1, ah2, ah3, b0, b1);
                mma_tf32(sacc[j], al0, al1, al2, al3, b0, b1);
            }
        }

        // ---- online softmax on register fragments
        float mx0 = -1e30f, mx1 = -1e30f;
        #pragma unroll
        for (int j = 0; j < 8; j++) {
            mx0 = fmaxf(mx0, fmaxf(sacc[j][0], sacc[j][1]));
            mx1 = fmaxf(mx1, fmaxf(sacc[j][2], sacc[j][3]));
        }
        #pragma unroll
        for (int off = 1; off < 4; off <<= 1) {
            mx0 = fmaxf(mx0, __shfl_xor_sync(0xffffffffu, mx0, off));
            mx1 = fmaxf(mx1, __shfl_xor_sync(0xffffffffu, mx1, off));
        }
        const float mn0 = fmaxf(m0, mx0);
        const float mn1 = fmaxf(m1, mx1);
        const float c0  = __expf(m0 - mn0);
        const float c1  = __expf(m1 - mn1);
        m0 = mn0; m1 = mn1;

        float ls0 = 0.f, ls1 = 0.f;
        #pragma unroll
        for (int j = 0; j < 8; j++) {
            sacc[j][0] = __expf(sacc[j][0] - mn0);
            sacc[j][1] = __expf(sacc[j][1] - mn0);
            sacc[j][2] = __expf(sacc[j][2] - mn1);
            sacc[j][3] = __expf(sacc[j][3] - mn1);
            ls0 += sacc[j][0] + sacc[j][1];
            ls1 += sacc[j][2] + sacc[j][3];
        }
        #pragma unroll
        for (int off = 1; off < 4; off <<= 1) {
            ls0 += __shfl_xor_sync(0xffffffffu, ls0, off);
            ls1 += __shfl_xor_sync(0xffffffffu, ls1, off);
        }
        l0 = l0 * c0 + ls0;
        l1 = l1 * c1 + ls1;
        #pragma unroll
        for (int j = 0; j < 4; j++) {
            O[j][0] *= c0; O[j][1] *= c0;
            O[j][2] *= c1; O[j][3] *= c1;
        }

        // ---- stage P (tf32-rounded) into per-warp smem slice
        #pragma unroll
        for (int j = 0; j < 8; j++) {
            float2 p01 = make_float2(tf32r(sacc[j][0]), tf32r(sacc[j][1]));
            float2 p23 = make_float2(tf32r(sacc[j][2]), tf32r(sacc[j][3]));
            *(float2*)&Psh[(prow    ) * PS + j * 8 + 2 * qd] = p01;
            *(float2*)&Psh[(prow + 8) * PS + j * 8 + 2 * qd] = p23;
        }
        __syncwarp();

        // ---- O += P @ V   (16x64 @ 64x32 per warp)
        #pragma unroll
        for (int kk = 0; kk < 8; kk++) {
            const int kc = kk * 8;
            unsigned a0 = __float_as_uint(Psh[(prow    ) * PS + kc + qd    ]);
            unsigned a1 = __float_as_uint(Psh[(prow + 8) * PS + kc + qd    ]);
            unsigned a2 = __float_as_uint(Psh[(prow    ) * PS + kc + qd + 4]);
            unsigned a3 = __float_as_uint(Psh[(prow + 8) * PS + kc + qd + 4]);
            #pragma unroll
            for (int j = 0; j < 4; j++) {
                unsigned b0 = __float_as_uint(Vsh[(kc + qd    ) * VS + j * 8 + g]);
                unsigned b1 = __float_as_uint(Vsh[(kc + qd + 4) * VS + j * 8 + g]);
                mma_tf32(O[j], a0, a1, a2, a3, b0, b1);
            }
        }
    }

    // ---- epilogue: normalize + store
    const float inv0 = 1.f / l0;
    const float inv1 = 1.f / l1;
    const size_t row0 = (size_t)(b * T_LEN + t0 + prow) * HID + h * DHEAD;
    const size_t row1 = row0 + (size_t)8 * HID;
    #pragma unroll
    for (int j = 0; j < 4; j++) {
        const int d0 = j * 8 + 2 * qd;
        *(float2*)&ao[row0 + d0] = make_float2(O[j][0] * inv0, O[j][1] * inv0);
        *(float2*)&ao[row1 + d0] = make_float2(O[j][2] * inv1, O[j][3] * inv1);
    }
}

// ---------------- launch ----------------
extern "C" void kernel_launch(void* const* d_in, const int* in_sizes, int n_in,
                              void* d_out, int out_size) {
    const float* x    = (const float*)d_in[0];
    const float* ctx  = (const float*)d_in[1];
    const float* w_q  = (const float*)d_in[2];
    const float* w_kv = (const float*)d_in[3];
    const float* w_o  = (const float*)d_in[4];
    const float* b_o  = (const float*)d_in[5];
    float* out = (float*)d_out;

    float* q  = nullptr; cudaGetSymbolAddress((void**)&q,  g_q);
    float* kv = nullptr; cudaGetSymbolAddress((void**)&kv, g_kv);
    float* ao = nullptr; cudaGetSymbolAddress((void**)&ao, g_ao);

    const int MQ = B_SZ * T_LEN;   // 8192
    const int MK = B_SZ * S_LEN;   // 16384

    const int attn_smem = (64 * QS * 2 + 64 * KS + 64 * VS + 64 * PS) * sizeof(float);
    cudaFuncSetAttribute(attn_tc_kernel,
                         cudaFuncAttributeMaxDynamicSharedMemorySize, attn_smem);

    gemm_tc_kernel<false><<<dim3(HID / 64, MQ / 64), 128>>>(x, w_q, nullptr, q, MQ, HID, DIM);
    gemm_tc_kernel<false><<<dim3(2 * HID / 64, MK / 64), 128>>>(ctx, w_kv, nullptr, kv, MK, 2 * HID, DIM);
    attn_tc_kernel<<<dim3(T_LEN / 64, HEADS, B_SZ), 128, attn_smem>>>(q, kv, ao);
    gemm_tc_kernel<true><<<dim3(DIM / 64, MQ / 64), 128>>>(ao, w_o, b_o, out, MQ, DIM, HID);
}

// round 5
// speedup vs baseline: 6.1715x; 1.7096x over previous
#include <cuda_runtime.h>
#include <cuda_bf16.h>
#include <math.h>

#define B_SZ   4
#define T_LEN  2048
#define S_LEN  4096
#define DIM    256
#define HEADS  8
#define DHEAD  32
#define HID    256
#define SCALE  0.17677669529663687f   // 32^-0.5

// ---------------- scratch (no allocation allowed) ----------------
__device__ float g_q [B_SZ * T_LEN * HID];
__device__ float g_kv[B_SZ * S_LEN * 2 * HID];
__device__ float g_ao[B_SZ * T_LEN * HID];

// ---------------- helpers ----------------
__device__ __forceinline__ float tf32r(float x) {
    unsigned int u;
    asm("cvt.rna.tf32.f32 %0, %1;" : "=r"(u) : "f"(x));
    return __uint_as_float(u);
}
__device__ __forceinline__ unsigned tf32u(float x) {
    unsigned int u;
    asm("cvt.rna.tf32.f32 %0, %1;" : "=r"(u) : "f"(x));
    return u;
}

__device__ __forceinline__ void mma_tf32(float* c,
                                         unsigned a0, unsigned a1, unsigned a2, unsigned a3,
                                         unsigned b0, unsigned b1) {
    asm volatile(
        "mma.sync.aligned.m16n8k8.row.col.f32.tf32.tf32.f32 "
        "{%0,%1,%2,%3}, {%4,%5,%6,%7}, {%8,%9}, {%0,%1,%2,%3};"
        : "+f"(c[0]), "+f"(c[1]), "+f"(c[2]), "+f"(c[3])
        : "r"(a0), "r"(a1), "r"(a2), "r"(a3), "r"(b0), "r"(b1));
}

__device__ __forceinline__ void cp16(float* smem_ptr, const float* gmem_ptr) {
    unsigned s = (unsigned)__cvta_generic_to_shared(smem_ptr);
    asm volatile("cp.async.cg.shared.global [%0], [%1], 16;" :: "r"(s), "l"(gmem_ptr));
}
#define CP_COMMIT() asm volatile("cp.async.commit_group;")
#define CP_WAIT(n)  asm volatile("cp.async.wait_group %0;" :: "n"(n))

// ---------------- tf32 GEMM, cp.async double-buffered ----------------
// C[M,N] = A[M,K] @ W[K,N] (+bias). 2-term tf32 split on A at fragment time.
// BM=128, BN=64, BK=32. 256 threads = 8 warps (4 row x 2 col), warp tile 32x32.
#define AS2 36   // A smem stride [m][k]
#define WS2 72   // W smem stride [k][n]  (72 % 32 == 8 -> conflict-free frags)
#define A_BUF (128 * AS2)
#define W_BUF (32 * WS2)

template<bool BIAS>
__global__ void gemm_tc_kernel(const float* __restrict__ A,
                               const float* __restrict__ W,
                               const float* __restrict__ bias,
                               float* __restrict__ C,
                               int M, int N, int K) {
    extern __shared__ float sg[];
    float* Asm = sg;               // 2 * 128*36
    float* Wsm = sg + 2 * A_BUF;   // 2 * 32*72

    const int tid  = threadIdx.x;
    const int warp = tid >> 5;
    const int lane = tid & 31;
    const int g    = lane >> 2;
    const int qd   = lane & 3;
    const int m0 = blockIdx.y * 128;
    const int n0 = blockIdx.x * 64;
    const int rm = (warp & 3) * 32;
    const int cn = (warp >> 2) * 32;

    const int a_row = tid >> 3, a_seg = (tid & 7) * 4;    // 32 rows/pass, 4 passes
    const int w_row = tid >> 4, w_seg = (tid & 15) * 4;   // 16 rows/pass, 2 passes

    float acc[2][4][4];
    #pragma unroll
    for (int mi = 0; mi < 2; mi++)
        #pragma unroll
        for (int ni = 0; ni < 4; ni++)
            #pragma unroll
            for (int i = 0; i < 4; i++) acc[mi][ni][i] = 0.f;

    auto load_tiles = [&](int buf, int k0) {
        float* Ab = Asm + buf * A_BUF;
        float* Wb = Wsm + buf * W_BUF;
        #pragma unroll
        for (int p = 0; p < 4; p++) {
            int r = p * 32 + a_row;
            cp16(&Ab[r * AS2 + a_seg], &A[(size_t)(m0 + r) * K + k0 + a_seg]);
        }
        #pragma unroll
        for (int p = 0; p < 2; p++) {
            int r = p * 16 + w_row;
            cp16(&Wb[r * WS2 + w_seg], &W[(size_t)(k0 + r) * N + n0 + w_seg]);
        }
    };

    const int n_iter = K / 32;          // K=256 -> 8
    load_tiles(0, 0);
    CP_COMMIT();

    for (int it = 0; it < n_iter; it++) {
        if (it + 1 < n_iter) {
            load_tiles((it + 1) & 1, (it + 1) * 32);
            CP_COMMIT();
            CP_WAIT(1);
        } else {
            CP_WAIT(0);
        }
        __syncthreads();

        const float* Ab = Asm + (it & 1) * A_BUF;
        const float* Wb = Wsm + (it & 1) * W_BUF;

        #pragma unroll
        for (int ks = 0; ks < 4; ks++) {
            const int kc = ks * 8;
            unsigned ah[2][4], al[2][4];
            #pragma unroll
            for (int mi = 0; mi < 2; mi++) {
                const int r = rm + mi * 16 + g;
                float r0 = Ab[(r    ) * AS2 + kc + qd    ];
                float r1 = Ab[(r + 8) * AS2 + kc + qd    ];
                float r2 = Ab[(r    ) * AS2 + kc + qd + 4];
                float r3 = Ab[(r + 8) * AS2 + kc + qd + 4];
                float h0 = tf32r(r0), h1 = tf32r(r1), h2 = tf32r(r2), h3 = tf32r(r3);
                ah[mi][0] = __float_as_uint(h0); al[mi][0] = tf32u(r0 - h0);
                ah[mi][1] = __float_as_uint(h1); al[mi][1] = tf32u(r1 - h1);
                ah[mi][2] = __float_as_uint(h2); al[mi][2] = tf32u(r2 - h2);
                ah[mi][3] = __float_as_uint(h3); al[mi][3] = tf32u(r3 - h3);
            }
            #pragma unroll
            for (int ni = 0; ni < 4; ni++) {
                const int n = cn + ni * 8 + g;
                unsigned b0 = tf32u(Wb[(kc + qd    ) * WS2 + n]);
                unsigned b1 = tf32u(Wb[(kc + qd + 4) * WS2 + n]);
                #pragma unroll
                for (int mi = 0; mi < 2; mi++) {
                    mma_tf32(acc[mi][ni], ah[mi][0], ah[mi][1], ah[mi][2], ah[mi][3], b0, b1);
                    mma_tf32(acc[mi][ni], al[mi][0], al[mi][1], al[mi][2], al[mi][3], b0, b1);
                }
            }
        }
        __syncthreads();
    }

    #pragma unroll
    for (int mi = 0; mi < 2; mi++) {
        const size_t r0 = (size_t)(m0 + rm + mi * 16 + g) * N;
        const size_t r1 = r0 + (size_t)8 * N;
        #pragma unroll
        for (int ni = 0; ni < 4; ni++) {
            const int col = n0 + cn + ni * 8 + 2 * qd;
            float b0v = 0.f, b1v = 0.f;
            if (BIAS) { b0v = bias[col]; b1v = bias[col + 1]; }
            *(float2*)&C[r0 + col] = make_float2(acc[mi][ni][0] + b0v, acc[mi][ni][1] + b1v);
            *(float2*)&C[r1 + col] = make_float2(acc[mi][ni][2] + b0v, acc[mi][ni][3] + b1v);
        }
    }
}

// ---------------- tensor-core flash attention ----------------
// grid (T/64, H, B), block 128 (4 warps, 16 q-rows each). BN=64, cp.async x2.
#define QS 36
#define KS 36
#define VS 40
#define PS 68
#define K_BUF (64 * KS)
#define V_BUF (64 * VS)

__global__ void attn_tc_kernel(const float* __restrict__ q,
                               const float* __restrict__ kv,
                               float* __restrict__ ao) {
    extern __shared__ float sm[];
    float* Ksh = sm;                     // 2 * 64*36
    float* Vsh = sm + 2 * K_BUF;         // 2 * 64*40
    float* Psh = sm + 2 * K_BUF + 2 * V_BUF;   // 64*68 (aliased as Q staging)

    const int b    = blockIdx.z;
    const int h    = blockIdx.y;
    const int t0   = blockIdx.x * 64;
    const int tid  = threadIdx.x;
    const int warp = tid >> 5;
    const int lane = tid & 31;
    const int g    = lane >> 2;
    const int qd   = lane & 3;
    const int prow = warp * 16 + g;

    const float* kvbase = kv + ((size_t)b * S_LEN) * (2 * HID) + h * DHEAD;
    const int lrow = tid >> 3, lseg = (tid & 7) * 4;   // 16 rows/pass

    // ---- stage Q (raw) into Psh area via cp.async, then hoist fragments
    {
        float* Qst = Psh;   // stride QS
        const float* qbase = q + ((size_t)(b * T_LEN + t0)) * HID + h * DHEAD;
        #pragma unroll
        for (int p = 0; p < 4; p++) {
            int r = p * 16 + lrow;
            cp16(&Qst[r * QS + lseg], &qbase[(size_t)r * HID + lseg]);
        }
        CP_COMMIT();
        CP_WAIT(0);
        __syncthreads();
    }

    unsigned qh[4][4], ql[4][4];
    #pragma unroll
    for (int ks = 0; ks < 4; ks++) {
        const int kc = ks * 8;
        const float* Qst = Psh;
        float r0 = Qst[(prow    ) * QS + kc + qd    ];
        float r1 = Qst[(prow + 8) * QS + kc + qd    ];
        float r2 = Qst[(prow    ) * QS + kc + qd + 4];
        float r3 = Qst[(prow + 8) * QS + kc + qd + 4];
        float h0 = tf32r(r0), h1 = tf32r(r1), h2 = tf32r(r2), h3 = tf32r(r3);
        qh[ks][0] = __float_as_uint(h0); ql[ks][0] = tf32u(r0 - h0);
        qh[ks][1] = __float_as_uint(h1); ql[ks][1] = tf32u(r1 - h1);
        qh[ks][2] = __float_as_uint(h2); ql[ks][2] = tf32u(r2 - h2);
        qh[ks][3] = __float_as_uint(h3); ql[ks][3] = tf32u(r3 - h3);
    }
    __syncthreads();   // Q reads done before Psh reused for P

    float m0 = -1e30f, m1 = -1e30f;
    float l0 = 0.f,    l1 = 0.f;
    float O[4][4];
    #pragma unroll
    for (int j = 0; j < 4; j++)
        #pragma unroll
        for (int i = 0; i < 4; i++) O[j][i] = 0.f;

    auto load_kv = [&](int buf, int s0) {
        float* Kb = Ksh + buf * K_BUF;
        float* Vb = Vsh + buf * V_BUF;
        #pragma unroll
        for (int p = 0; p < 4; p++) {
            int r = p * 16 + lrow;
            const float* src = kvbase + (size_t)(s0 + r) * (2 * HID) + lseg;
            cp16(&Kb[r * KS + lseg], src);
            cp16(&Vb[r * VS + lseg], src + HID);
        }
    };

    const int n_chunks = S_LEN / 64;   // 64
    load_kv(0, 0);
    CP_COMMIT();

    for (int it = 0; it < n_chunks; it++) {
        if (it + 1 < n_chunks) {
            load_kv((it + 1) & 1, (it + 1) * 64);
            CP_COMMIT();
            CP_WAIT(1);
        } else {
            CP_WAIT(0);
        }
        __syncthreads();

        const float* Kb = Ksh + (it & 1) * K_BUF;
        const float* Vb = Vsh + (it & 1) * V_BUF;

        // ---- S = Q @ K^T (2-term split, K tf32 on the fly)
        float sacc[8][4];
        #pragma unroll
        for (int j = 0; j < 8; j++)
            #pragma unroll
            for (int i = 0; i < 4; i++) sacc[j][i] = 0.f;

        #pragma unroll
        for (int ks = 0; ks < 4; ks++) {
            const int kc = ks * 8;
            #pragma unroll
            for (int j = 0; j < 8; j++) {
                const int nr = j * 8 + g;
                unsigned b0 = tf32u(Kb[nr * KS + kc + qd    ]);
                unsigned b1 = tf32u(Kb[nr * KS + kc + qd + 4]);
                mma_tf32(sacc[j], qh[ks][0], qh[ks][1], qh[ks][2], qh[ks][3], b0, b1);
                mma_tf32(sacc[j], ql[ks][0], ql[ks][1], ql[ks][2], ql[ks][3], b0, b1);
            }
        }
        #pragma unroll
        for (int j = 0; j < 8; j++)
            #pragma unroll
            for (int i = 0; i < 4; i++) sacc[j][i] *= SCALE;

        // ---- online softmax
        float mx0 = -1e30f, mx1 = -1e30f;
        #pragma unroll
        for (int j = 0; j < 8; j++) {
            mx0 = fmaxf(mx0, fmaxf(sacc[j][0], sacc[j][1]));
            mx1 = fmaxf(mx1, fmaxf(sacc[j][2], sacc[j][3]));
        }
        #pragma unroll
        for (int off = 1; off < 4; off <<= 1) {
            mx0 = fmaxf(mx0, __shfl_xor_sync(0xffffffffu, mx0, off));
            mx1 = fmaxf(mx1, __shfl_xor_sync(0xffffffffu, mx1, off));
        }
        const float mn0 = fmaxf(m0, mx0);
        const float mn1 = fmaxf(m1, mx1);
        const float c0  = __expf(m0 - mn0);
        const float c1  = __expf(m1 - mn1);
        m0 = mn0; m1 = mn1;

        float ls0 = 0.f, ls1 = 0.f;
        #pragma unroll
        for (int j = 0; j < 8; j++) {
            sacc[j][0] = __expf(sacc[j][0] - mn0);
            sacc[j][1] = __expf(sacc[j][1] - mn0);
            sacc[j][2] = __expf(sacc[j][2] - mn1);
            sacc[j][3] = __expf(sacc[j][3] - mn1);
            ls0 += sacc[j][0] + sacc[j][1];
            ls1 += sacc[j][2] + sacc[j][3];
        }
        #pragma unroll
        for (int off = 1; off < 4; off <<= 1) {
            ls0 += __shfl_xor_sync(0xffffffffu, ls0, off);
            ls1 += __shfl_xor_sync(0xffffffffu, ls1, off);
        }
        l0 = l0 * c0 + ls0;
        l1 = l1 * c1 + ls1;
        #pragma unroll
        for (int j = 0; j < 4; j++) {
            O[j][0] *= c0; O[j][1] *= c0;
            O[j][2] *= c1; O[j][3] *= c1;
        }

        // ---- stage P (tf32) per-warp
        #pragma unroll
        for (int j = 0; j < 8; j++) {
            float2 p01 = make_float2(tf32r(sacc[j][0]), tf32r(sacc[j][1]));
            float2 p23 = make_float2(tf32r(sacc[j][2]), tf32r(sacc[j][3]));
            *(float2*)&Psh[(prow    ) * PS + j * 8 + 2 * qd] = p01;
            *(float2*)&Psh[(prow + 8) * PS + j * 8 + 2 * qd] = p23;
        }
        __syncwarp();

        // ---- O += P @ V (V tf32 on the fly)
        #pragma unroll
        for (int kk = 0; kk < 8; kk++) {
            const int kc = kk * 8;
            unsigned a0 = __float_as_uint(Psh[(prow    ) * PS + kc + qd    ]);
            unsigned a1 = __float_as_uint(Psh[(prow + 8) * PS + kc + qd    ]);
            unsigned a2 = __float_as_uint(Psh[(prow    ) * PS + kc + qd + 4]);
            unsigned a3 = __float_as_uint(Psh[(prow + 8) * PS + kc + qd + 4]);
            #pragma unroll
            for (int j = 0; j < 4; j++) {
                unsigned b0 = tf32u(Vb[(kc + qd    ) * VS + j * 8 + g]);
                unsigned b1 = tf32u(Vb[(kc + qd + 4) * VS + j * 8 + g]);
                mma_tf32(O[j], a0, a1, a2, a3, b0, b1);
            }
        }
        __syncthreads();
    }

    const float inv0 = 1.f / l0;
    const float inv1 = 1.f / l1;
    const size_t row0 = (size_t)(b * T_LEN + t0 + prow) * HID + h * DHEAD;
    const size_t row1 = row0 + (size_t)8 * HID;
    #pragma unroll
    for (int j = 0; j < 4; j++) {
        const int d0 = j * 8 + 2 * qd;
        *(float2*)&ao[row0 + d0] = make_float2(O[j][0] * inv0, O[j][1] * inv0);
        *(float2*)&ao[row1 + d0] = make_float2(O[j][2] * inv1, O[j][3] * inv1);
    }
}

// ---------------- launch ----------------
extern "C" void kernel_launch(void* const* d_in, const int* in_sizes, int n_in,
                              void* d_out, int out_size) {
    const float* x    = (const float*)d_in[0];
    const float* ctx  = (const float*)d_in[1];
    const float* w_q  = (const float*)d_in[2];
    const float* w_kv = (const float*)d_in[3];
    const float* w_o  = (const float*)d_in[4];
    const float* b_o  = (const float*)d_in[5];
    float* out = (float*)d_out;

    float* q  = nullptr; cudaGetSymbolAddress((void**)&q,  g_q);
    float* kv = nullptr; cudaGetSymbolAddress((void**)&kv, g_kv);
    float* ao = nullptr; cudaGetSymbolAddress((void**)&ao, g_ao);

    const int MQ = B_SZ * T_LEN;   // 8192
    const int MK = B_SZ * S_LEN;   // 16384

    const int gemm_smem = (2 * A_BUF + 2 * W_BUF) * sizeof(float);        // 55296
    const int attn_smem = (2 * K_BUF + 2 * V_BUF + 64 * PS) * sizeof(float); // 56320

    cudaFuncSetAttribute(gemm_tc_kernel<false>,
                         cudaFuncAttributeMaxDynamicSharedMemorySize, gemm_smem);
    cudaFuncSetAttribute(gemm_tc_kernel<true>,
                         cudaFuncAttributeMaxDynamicSharedMemorySize, gemm_smem);
    cudaFuncSetAttribute(attn_tc_kernel,
                         cudaFuncAttributeMaxDynamicSharedMemorySize, attn_smem);

    gemm_tc_kernel<false><<<dim3(HID / 64, MQ / 128), 256, gemm_smem>>>(x, w_q, nullptr, q, MQ, HID, DIM);
    gemm_tc_kernel<false><<<dim3(2 * HID / 64, MK / 128), 256, gemm_smem>>>(ctx, w_kv, nullptr, kv, MK, 2 * HID, DIM);
    attn_tc_kernel<<<dim3(T_LEN / 64, HEADS, B_SZ), 128, attn_smem>>>(q, kv, ao);
    gemm_tc_kernel<true><<<dim3(DIM / 64, MQ / 128), 256, gemm_smem>>>(ao, w_o, b_o, out, MQ, DIM, HID);
}

// round 7
// speedup vs baseline: 6.3951x; 1.0362x over previous
#include <cuda_runtime.h>
#include <cuda_bf16.h>
#include <math.h>

#define B_SZ   4
#define T_LEN  2048
#define S_LEN  4096
#define DIM    256
#define HEADS  8
#define DHEAD  32
#define HID    256
#define SCALE  0.17677669529663687f   // 32^-0.5
#define QSCALE 0.25505567633920995f   // SCALE * log2(e)

// ---------------- scratch (no allocation allowed) ----------------
__device__ float g_q [B_SZ * T_LEN * HID];
__device__ float g_kv[B_SZ * S_LEN * 2 * HID];   // K half col-permuted (pK), V half (pV), tf32-rounded
__device__ float g_ao[B_SZ * T_LEN * HID];

// ---------------- helpers ----------------
__device__ __forceinline__ float tf32r(float x) {
    unsigned int u;
    asm("cvt.rna.tf32.f32 %0, %1;" : "=r"(u) : "f"(x));
    return __uint_as_float(u);
}
__device__ __forceinline__ unsigned tf32u(float x) {
    unsigned int u;
    asm("cvt.rna.tf32.f32 %0, %1;" : "=r"(u) : "f"(x));
    return u;
}

__device__ __forceinline__ void mma_tf32(float* c,
                                         unsigned a0, unsigned a1, unsigned a2, unsigned a3,
                                         unsigned b0, unsigned b1) {
    asm volatile(
        "mma.sync.aligned.m16n8k8.row.col.f32.tf32.tf32.f32 "
        "{%0,%1,%2,%3}, {%4,%5,%6,%7}, {%8,%9}, {%0,%1,%2,%3};"
        : "+f"(c[0]), "+f"(c[1]), "+f"(c[2]), "+f"(c[3])
        : "r"(a0), "r"(a1), "r"(a2), "r"(a3), "r"(b0), "r"(b1));
}

__device__ __forceinline__ void cp16(float* smem_ptr, const float* gmem_ptr) {
    unsigned s = (unsigned)__cvta_generic_to_shared(smem_ptr);
    asm volatile("cp.async.cg.shared.global [%0], [%1], 16;" :: "r"(s), "l"(gmem_ptr));
}
#define CP_COMMIT() asm volatile("cp.async.commit_group;")
#define CP_WAIT(n)  asm volatile("cp.async.wait_group %0;" :: "n"(n))

// within-head column permutations (storage position for logical d)
__device__ __forceinline__ int permK(int d) {   // (kc+qd, kc+qd+4) -> adjacent
    return (d >> 3) * 8 + (d & 3) * 2 + ((d >> 2) & 1);
}
__device__ __forceinline__ int permV(int d) {   // j*8+g -> g*4+j
    return (d & 7) * 4 + (d >> 3);
}

// ---------------- tf32 GEMM, cp.async double-buffered ----------------
// MODE: 0 = plain fp32 store, 1 = tf32-round + KV column-perm store, 2 = +bias
#define AS2 36
#define WS2 72
#define A_BUF (128 * AS2)
#define W_BUF (32 * WS2)

template<int MODE>
__global__ void gemm_tc_kernel(const float* __restrict__ A,
                               const float* __restrict__ W,
                               const float* __restrict__ bias,
                               float* __restrict__ C,
                               int M, int N, int K) {
    extern __shared__ float sg[];
    float* Asm = sg;
    float* Wsm = sg + 2 * A_BUF;

    const int tid  = threadIdx.x;
    const int warp = tid >> 5;
    const int lane = tid & 31;
    const int g    = lane >> 2;
    const int qd   = lane & 3;
    const int m0 = blockIdx.y * 128;
    const int n0 = blockIdx.x * 64;
    const int rm = (warp & 3) * 32;
    const int cn = (warp >> 2) * 32;

    const int a_row = tid >> 3, a_seg = (tid & 7) * 4;
    const int w_row = tid >> 4, w_seg = (tid & 15) * 4;

    float acc[2][4][4];
    #pragma unroll
    for (int mi = 0; mi < 2; mi++)
        #pragma unroll
        for (int ni = 0; ni < 4; ni++)
            #pragma unroll
            for (int i = 0; i < 4; i++) acc[mi][ni][i] = 0.f;

    auto load_tiles = [&](int buf, int k0) {
        float* Ab = Asm + buf * A_BUF;
        float* Wb = Wsm + buf * W_BUF;
        #pragma unroll
        for (int p = 0; p < 4; p++) {
            int r = p * 32 + a_row;
            cp16(&Ab[r * AS2 + a_seg], &A[(size_t)(m0 + r) * K + k0 + a_seg]);
        }
        #pragma unroll
        for (int p = 0; p < 2; p++) {
            int r = p * 16 + w_row;
            cp16(&Wb[r * WS2 + w_seg], &W[(size_t)(k0 + r) * N + n0 + w_seg]);
        }
    };

    const int n_iter = K / 32;
    load_tiles(0, 0);
    CP_COMMIT();

    for (int it = 0; it < n_iter; it++) {
        if (it + 1 < n_iter) {
            load_tiles((it + 1) & 1, (it + 1) * 32);
            CP_COMMIT();
            CP_WAIT(1);
        } else {
            CP_WAIT(0);
        }
        __syncthreads();

        const float* Ab = Asm + (it & 1) * A_BUF;
        const float* Wb = Wsm + (it & 1) * W_BUF;

        #pragma unroll
        for (int ks = 0; ks < 4; ks++) {
            const int kc = ks * 8;
            unsigned ah[2][4], al[2][4];
            #pragma unroll
            for (int mi = 0; mi < 2; mi++) {
                const int r = rm + mi * 16 + g;
                float r0 = Ab[(r    ) * AS2 + kc + qd    ];
                float r1 = Ab[(r + 8) * AS2 + kc + qd    ];
                float r2 = Ab[(r    ) * AS2 + kc + qd + 4];
                float r3 = Ab[(r + 8) * AS2 + kc + qd + 4];
                float h0 = tf32r(r0), h1 = tf32r(r1), h2 = tf32r(r2), h3 = tf32r(r3);
                ah[mi][0] = __float_as_uint(h0); al[mi][0] = tf32u(r0 - h0);
                ah[mi][1] = __float_as_uint(h1); al[mi][1] = tf32u(r1 - h1);
                ah[mi][2] = __float_as_uint(h2); al[mi][2] = tf32u(r2 - h2);
                ah[mi][3] = __float_as_uint(h3); al[mi][3] = tf32u(r3 - h3);
            }
            #pragma unroll
            for (int ni = 0; ni < 4; ni++) {
                const int n = cn + ni * 8 + g;
                unsigned b0 = tf32u(Wb[(kc + qd    ) * WS2 + n]);
                unsigned b1 = tf32u(Wb[(kc + qd + 4) * WS2 + n]);
                #pragma unroll
                for (int mi = 0; mi < 2; mi++) {
                    mma_tf32(acc[mi][ni], ah[mi][0], ah[mi][1], ah[mi][2], ah[mi][3], b0, b1);
                    mma_tf32(acc[mi][ni], al[mi][0], al[mi][1], al[mi][2], al[mi][3], b0, b1);
                }
            }
        }
        __syncthreads();
    }

    #pragma unroll
    for (int mi = 0; mi < 2; mi++) {
        const size_t r0 = (size_t)(m0 + rm + mi * 16 + g) * N;
        const size_t r1 = r0 + (size_t)8 * N;
        #pragma unroll
        for (int ni = 0; ni < 4; ni++) {
            const int col = n0 + cn + ni * 8 + 2 * qd;
            if (MODE == 1) {
                // tf32-round + per-half column permutation (K: permK, V: permV)
                #pragma unroll
                for (int c2 = 0; c2 < 2; c2++) {
                    const int c  = col + c2;
                    const int d  = c & 31;
                    const int pd = (c < HID) ? permK(d) : permV(d);
                    const int pc = (c & ~31) | pd;
                    C[r0 + pc] = tf32r(acc[mi][ni][0 + c2]);
                    C[r1 + pc] = tf32r(acc[mi][ni][2 + c2]);
                }
            } else {
                float b0v = 0.f, b1v = 0.f;
                if (MODE == 2) { b0v = bias[col]; b1v = bias[col + 1]; }
                *(float2*)&C[r0 + col] = make_float2(acc[mi][ni][0] + b0v, acc[mi][ni][1] + b1v);
                *(float2*)&C[r1 + col] = make_float2(acc[mi][ni][2] + b0v, acc[mi][ni][3] + b1v);
            }
        }
    }
}

// ---------------- tensor-core flash attention ----------------
// grid (T/64, H, B), block 128 (4 warps, 16 q-rows). K/V pre-rounded+permuted in gmem.
#define QS 36
#define KS 36
#define VS 40
#define PS 68
#define K_BUF (64 * KS)
#define V_BUF (64 * VS)

__global__ void attn_tc_kernel(const float* __restrict__ q,
                               const float* __restrict__ kv,
                               float* __restrict__ ao) {
    extern __shared__ float sm[];
    float* Ksh = sm;
    float* Vsh = sm + 2 * K_BUF;
    float* Psh = sm + 2 * K_BUF + 2 * V_BUF;

    const int b    = blockIdx.z;
    const int h    = blockIdx.y;
    const int t0   = blockIdx.x * 64;
    const int tid  = threadIdx.x;
    const int warp = tid >> 5;
    const int lane = tid & 31;
    const int g    = lane >> 2;
    const int qd   = lane & 3;
    const int prow = warp * 16 + g;

    const float* kvbase = kv + ((size_t)b * S_LEN) * (2 * HID) + h * DHEAD;
    const int lrow = tid >> 3, lseg = (tid & 7) * 4;

    // ---- stage Q (raw fp32) into Psh, hoist fragments with QSCALE + hi/lo split
    {
        float* Qst = Psh;
        const float* qbase = q + ((size_t)(b * T_LEN + t0)) * HID + h * DHEAD;
        #pragma unroll
        for (int p = 0; p < 4; p++) {
            int r = p * 16 + lrow;
            cp16(&Qst[r * QS + lseg], &qbase[(size_t)r * HID + lseg]);
        }
        CP_COMMIT();
        CP_WAIT(0);
        __syncthreads();
    }

    unsigned qh[4][4], ql[4][4];
    #pragma unroll
    for (int ks = 0; ks < 4; ks++) {
        const int kc = ks * 8;
        const float* Qst = Psh;
        float r0 = Qst[(prow    ) * QS + kc + qd    ] * QSCALE;
        float r1 = Qst[(prow + 8) * QS + kc + qd    ] * QSCALE;
        float r2 = Qst[(prow    ) * QS + kc + qd + 4] * QSCALE;
        float r3 = Qst[(prow + 8) * QS + kc + qd + 4] * QSCALE;
        float h0 = tf32r(r0), h1 = tf32r(r1), h2 = tf32r(r2), h3 = tf32r(r3);
        qh[ks][0] = __float_as_uint(h0); ql[ks][0] = tf32u(r0 - h0);
        qh[ks][1] = __float_as_uint(h1); ql[ks][1] = tf32u(r1 - h1);
        qh[ks][2] = __float_as_uint(h2); ql[ks][2] = tf32u(r2 - h2);
        qh[ks][3] = __float_as_uint(h3); ql[ks][3] = tf32u(r3 - h3);
    }
    __syncthreads();

    float m0 = -1e30f, m1 = -1e30f;
    float l0 = 0.f,    l1 = 0.f;
    float O[4][4];
    #pragma unroll
    for (int j = 0; j < 4; j++)
        #pragma unroll
        for (int i = 0; i < 4; i++) O[j][i] = 0.f;

    auto load_kv = [&](int buf, int s0) {
        float* Kb = Ksh + buf * K_BUF;
        float* Vb = Vsh + buf * V_BUF;
        #pragma unroll
        for (int p = 0; p < 4; p++) {
            int r = p * 16 + lrow;
            const float* src = kvbase + (size_t)(s0 + r) * (2 * HID) + lseg;
            cp16(&Kb[r * KS + lseg], src);
            cp16(&Vb[r * VS + lseg], src + HID);
        }
    };

    const int n_chunks = S_LEN / 64;
    load_kv(0, 0);
    CP_COMMIT();

    for (int it = 0; it < n_chunks; it++) {
        if (it + 1 < n_chunks) {
            load_kv((it + 1) & 1, (it + 1) * 64);
            CP_COMMIT();
            CP_WAIT(1);
        } else {
            CP_WAIT(0);
        }
        __syncthreads();

        const float* Kb = Ksh + (it & 1) * K_BUF;
        const float* Vb = Vsh + (it & 1) * V_BUF;

        // ---- S(log2) = Q @ K^T : K frags via LDS.64 (permK layout), no cvt
        float sacc[8][4];
        #pragma unroll
        for (int j = 0; j < 8; j++)
            #pragma unroll
            for (int i = 0; i < 4; i++) sacc[j][i] = 0.f;

        #pragma unroll
        for (int ks = 0; ks < 4; ks++) {
            const int kc = ks * 8;
            #pragma unroll
            for (int j = 0; j < 8; j++) {
                const int nr = j * 8 + g;
                float2 kf = *(const float2*)&Kb[nr * KS + kc + 2 * qd];
                unsigned b0 = __float_as_uint(kf.x);
                unsigned b1 = __float_as_uint(kf.y);
                mma_tf32(sacc[j], qh[ks][0], qh[ks][1], qh[ks][2], qh[ks][3], b0, b1);
                mma_tf32(sacc[j], ql[ks][0], ql[ks][1], ql[ks][2], ql[ks][3], b0, b1);
            }
        }

        // ---- online softmax (exp2 domain)
        float mx0 = -1e30f, mx1 = -1e30f;
        #pragma unroll
        for (int j = 0; j < 8; j++) {
            mx0 = fmaxf(mx0, fmaxf(sacc[j][0], sacc[j][1]));
            mx1 = fmaxf(mx1, fmaxf(sacc[j][2], sacc[j][3]));
        }
        #pragma unroll
        for (int off = 1; off < 4; off <<= 1) {
            mx0 = fmaxf(mx0, __shfl_xor_sync(0xffffffffu, mx0, off));
            mx1 = fmaxf(mx1, __shfl_xor_sync(0xffffffffu, mx1, off));
        }
        const float mn0 = fmaxf(m0, mx0);
        const float mn1 = fmaxf(m1, mx1);
        const float c0  = exp2f(m0 - mn0);
        const float c1  = exp2f(m1 - mn1);
        m0 = mn0; m1 = mn1;

        float ls0 = 0.f, ls1 = 0.f;
        #pragma unroll
        for (int j = 0; j < 8; j++) {
            sacc[j][0] = exp2f(sacc[j][0] - mn0);
            sacc[j][1] = exp2f(sacc[j][1] - mn0);
            sacc[j][2] = exp2f(sacc[j][2] - mn1);
            sacc[j][3] = exp2f(sacc[j][3] - mn1);
            ls0 += sacc[j][0] + sacc[j][1];
            ls1 += sacc[j][2] + sacc[j][3];
        }
        #pragma unroll
        for (int off = 1; off < 4; off <<= 1) {
            ls0 += __shfl_xor_sync(0xffffffffu, ls0, off);
            ls1 += __shfl_xor_sync(0xffffffffu, ls1, off);
        }
        l0 = l0 * c0 + ls0;
        l1 = l1 * c1 + ls1;
        #pragma unroll
        for (int j = 0; j < 4; j++) {
            O[j][0] *= c0; O[j][1] *= c0;
            O[j][2] *= c1; O[j][3] *= c1;
        }

        // ---- stage P (tf32) per-warp
        #pragma unroll
        for (int j = 0; j < 8; j++) {
            float2 p01 = make_float2(tf32r(sacc[j][0]), tf32r(sacc[j][1]));
            float2 p23 = make_float2(tf32r(sacc[j][2]), tf32r(sacc[j][3]));
            *(float2*)&Psh[(prow    ) * PS + j * 8 + 2 * qd] = p01;
            *(float2*)&Psh[(prow + 8) * PS + j * 8 + 2 * qd] = p23;
        }
        __syncwarp();

        // ---- O += P @ V : V frags via LDS.128 (permV layout), no cvt
        #pragma unroll
        for (int kk = 0; kk < 8; kk++) {
            const int kc = kk * 8;
            unsigned a0 = __float_as_uint(Psh[(prow    ) * PS + kc + qd    ]);
            unsigned a1 = __float_as_uint(Psh[(prow + 8) * PS + kc + qd    ]);
            unsigned a2 = __float_as_uint(Psh[(prow    ) * PS + kc + qd + 4]);
            unsigned a3 = __float_as_uint(Psh[(prow + 8) * PS + kc + qd + 4]);
            float4 vf0 = *(const float4*)&Vb[(kc + qd    ) * VS + g * 4];
            float4 vf1 = *(const float4*)&Vb[(kc + qd + 4) * VS + g * 4];
            const float* v0 = &vf0.x;
            const float* v1 = &vf1.x;
            #pragma unroll
            for (int j = 0; j < 4; j++) {
                mma_tf32(O[j], a0, a1, a2, a3,
                         __float_as_uint(v0[j]), __float_as_uint(v1[j]));
            }
        }
        __syncthreads();
    }

    const float inv0 = 1.f / l0;
    const float inv1 = 1.f / l1;
    const size_t row0 = (size_t)(b * T_LEN + t0 + prow) * HID + h * DHEAD;
    const size_t row1 = row0 + (size_t)8 * HID;
    #pragma unroll
    for (int j = 0; j < 4; j++) {
        const int d0 = j * 8 + 2 * qd;
        *(float2*)&ao[row0 + d0] = make_float2(O[j][0] * inv0, O[j][1] * inv0);
        *(float2*)&ao[row1 + d0] = make_float2(O[j][2] * inv1, O[j][3] * inv1);
    }
}

// ---------------- launch ----------------
extern "C" void kernel_launch(void* const* d_in, const int* in_sizes, int n_in,
                              void* d_out, int out_size) {
    const float* x    = (const float*)d_in[0];
    const float* ctx  = (const float*)d_in[1];
    const float* w_q  = (const float*)d_in[2];
    const float* w_kv = (const float*)d_in[3];
    const float* w_o  = (const float*)d_in[4];
    const float* b_o  = (const float*)d_in[5];
    float* out = (float*)d_out;

    float* q  = nullptr; cudaGetSymbolAddress((void**)&q,  g_q);
    float* kv = nullptr; cudaGetSymbolAddress((void**)&kv, g_kv);
    float* ao = nullptr; cudaGetSymbolAddress((void**)&ao, g_ao);

    const int MQ = B_SZ * T_LEN;   // 8192
    const int MK = B_SZ * S_LEN;   // 16384

    const int gemm_smem = (2 * A_BUF + 2 * W_BUF) * sizeof(float);
    const int attn_smem = (2 * K_BUF + 2 * V_BUF + 64 * PS) * sizeof(float);

    cudaFuncSetAttribute(gemm_tc_kernel<0>,
                         cudaFuncAttributeMaxDynamicSharedMemorySize, gemm_smem);
    cudaFuncSetAttribute(gemm_tc_kernel<1>,
                         cudaFuncAttributeMaxDynamicSharedMemorySize, gemm_smem);
    cudaFuncSetAttribute(gemm_tc_kernel<2>,
                         cudaFuncAttributeMaxDynamicSharedMemorySize, gemm_smem);
    cudaFuncSetAttribute(attn_tc_kernel,
                         cudaFuncAttributeMaxDynamicSharedMemorySize, attn_smem);

    gemm_tc_kernel<0><<<dim3(HID / 64, MQ / 128), 256, gemm_smem>>>(x, w_q, nullptr, q, MQ, HID, DIM);
    gemm_tc_kernel<1><<<dim3(2 * HID / 64, MK / 128), 256, gemm_smem>>>(ctx, w_kv, nullptr, kv, MK, 2 * HID, DIM);
    attn_tc_kernel<<<dim3(T_LEN / 64, HEADS, B_SZ), 128, attn_smem>>>(q, kv, ao);
    gemm_tc_kernel<2><<<dim3(DIM / 64, MQ / 128), 256, gemm_smem>>>(ao, w_o, b_o, out, MQ, DIM, HID);
}

// round 9
// speedup vs baseline: 7.6267x; 1.1926x over previous
#include <cuda_runtime.h>
#include <cuda_bf16.h>
#include <cuda_fp16.h>
#include <math.h>

#define B_SZ   4
#define T_LEN  2048
#define S_LEN  4096
#define DIM    256
#define HEADS  8
#define DHEAD  32
#define HID    256
#define SCALE  0.17677669529663687f   // 32^-0.5
#define QSCALE 0.25505567633920995f   // SCALE * log2(e)

// ---------------- scratch (no allocation allowed) ----------------
__device__ float  g_q [B_SZ * T_LEN * HID];
__device__ float  g_kv[B_SZ * S_LEN * 2 * HID];             // K half: tf32-rounded + permK; V half unused
__device__ __half g_vt[B_SZ * HEADS * DHEAD * S_LEN];       // V fp16, transposed [b][h][d][s]
__device__ float  g_ao[B_SZ * T_LEN * HID];

// ---------------- helpers ----------------
__device__ __forceinline__ float tf32r(float x) {
    unsigned int u;
    asm("cvt.rna.tf32.f32 %0, %1;" : "=r"(u) : "f"(x));
    return __uint_as_float(u);
}
__device__ __forceinline__ unsigned tf32u(float x) {
    unsigned int u;
    asm("cvt.rna.tf32.f32 %0, %1;" : "=r"(u) : "f"(x));
    return u;
}
__device__ __forceinline__ unsigned packh2(float lo, float hi) {
    __half2 h = __floats2half2_rn(lo, hi);
    return *(unsigned*)&h;
}

__device__ __forceinline__ void mma_tf32(float* c,
                                         unsigned a0, unsigned a1, unsigned a2, unsigned a3,
                                         unsigned b0, unsigned b1) {
    asm volatile(
        "mma.sync.aligned.m16n8k8.row.col.f32.tf32.tf32.f32 "
        "{%0,%1,%2,%3}, {%4,%5,%6,%7}, {%8,%9}, {%0,%1,%2,%3};"
        : "+f"(c[0]), "+f"(c[1]), "+f"(c[2]), "+f"(c[3])
        : "r"(a0), "r"(a1), "r"(a2), "r"(a3), "r"(b0), "r"(b1));
}
__device__ __forceinline__ void mma_f16(float* c,
                                        unsigned a0, unsigned a1, unsigned a2, unsigned a3,
                                        unsigned b0, unsigned b1) {
    asm volatile(
        "mma.sync.aligned.m16n8k16.row.col.f32.f16.f16.f32 "
        "{%0,%1,%2,%3}, {%4,%5,%6,%7}, {%8,%9}, {%0,%1,%2,%3};"
        : "+f"(c[0]), "+f"(c[1]), "+f"(c[2]), "+f"(c[3])
        : "r"(a0), "r"(a1), "r"(a2), "r"(a3), "r"(b0), "r"(b1));
}

__device__ __forceinline__ void cp16(void* smem_ptr, const void* gmem_ptr) {
    unsigned s = (unsigned)__cvta_generic_to_shared(smem_ptr);
    asm volatile("cp.async.cg.shared.global [%0], [%1], 16;" :: "r"(s), "l"(gmem_ptr));
}
#define CP_COMMIT() asm volatile("cp.async.commit_group;")
#define CP_WAIT(n)  asm volatile("cp.async.wait_group %0;" :: "n"(n))

// within-head column permutation for K (storage position for logical d)
__device__ __forceinline__ int permK(int d) {   // (kc+qd, kc+qd+4) -> adjacent
    return (d >> 3) * 8 + (d & 3) * 2 + ((d >> 2) & 1);
}

// ---------------- tf32 GEMM, cp.async double-buffered ----------------
// MODE: 0 = plain fp32 store, 1 = KV store (K: tf32+permK into C; V: fp16 transposed into vt), 2 = +bias
#define AS2 36
#define WS2 72
#define A_BUF (128 * AS2)
#define W_BUF (32 * WS2)

template<int MODE>
__global__ void gemm_tc_kernel(const float* __restrict__ A,
                               const float* __restrict__ W,
                               const float* __restrict__ bias,
                               float* __restrict__ C,
                               __half* __restrict__ vt,
                               int M, int N, int K) {
    extern __shared__ float sg[];
    float* Asm = sg;
    float* Wsm = sg + 2 * A_BUF;

    const int tid  = threadIdx.x;
    const int warp = tid >> 5;
    const int lane = tid & 31;
    const int g    = lane >> 2;
    const int qd   = lane & 3;
    const int m0 = blockIdx.y * 128;
    const int n0 = blockIdx.x * 64;
    const int rm = (warp & 3) * 32;
    const int cn = (warp >> 2) * 32;

    const int a_row = tid >> 3, a_seg = (tid & 7) * 4;
    const int w_row = tid >> 4, w_seg = (tid & 15) * 4;

    float acc[2][4][4];
    #pragma unroll
    for (int mi = 0; mi < 2; mi++)
        #pragma unroll
        for (int ni = 0; ni < 4; ni++)
            #pragma unroll
            for (int i = 0; i < 4; i++) acc[mi][ni][i] = 0.f;

    auto load_tiles = [&](int buf, int k0) {
        float* Ab = Asm + buf * A_BUF;
        float* Wb = Wsm + buf * W_BUF;
        #pragma unroll
        for (int p = 0; p < 4; p++) {
            int r = p * 32 + a_row;
            cp16(&Ab[r * AS2 + a_seg], &A[(size_t)(m0 + r) * K + k0 + a_seg]);
        }
        #pragma unroll
        for (int p = 0; p < 2; p++) {
            int r = p * 16 + w_row;
            cp16(&Wb[r * WS2 + w_seg], &W[(size_t)(k0 + r) * N + n0 + w_seg]);
        }
    };

    const int n_iter = K / 32;
    load_tiles(0, 0);
    CP_COMMIT();

    for (int it = 0; it < n_iter; it++) {
        if (it + 1 < n_iter) {
            load_tiles((it + 1) & 1, (it + 1) * 32);
            CP_COMMIT();
            CP_WAIT(1);
        } else {
            CP_WAIT(0);
        }
        __syncthreads();

        const float* Ab = Asm + (it & 1) * A_BUF;
        const float* Wb = Wsm + (it & 1) * W_BUF;

        #pragma unroll
        for (int ks = 0; ks < 4; ks++) {
            const int kc = ks * 8;
            unsigned ah[2][4], al[2][4];
            #pragma unroll
            for (int mi = 0; mi < 2; mi++) {
                const int r = rm + mi * 16 + g;
                float r0 = Ab[(r    ) * AS2 + kc + qd    ];
                float r1 = Ab[(r + 8) * AS2 + kc + qd    ];
                float r2 = Ab[(r    ) * AS2 + kc + qd + 4];
                float r3 = Ab[(r + 8) * AS2 + kc + qd + 4];
                float h0 = tf32r(r0), h1 = tf32r(r1), h2 = tf32r(r2), h3 = tf32r(r3);
                ah[mi][0] = __float_as_uint(h0); al[mi][0] = tf32u(r0 - h0);
                ah[mi][1] = __float_as_uint(h1); al[mi][1] = tf32u(r1 - h1);
                ah[mi][2] = __float_as_uint(h2); al[mi][2] = tf32u(r2 - h2);
                ah[mi][3] = __float_as_uint(h3); al[mi][3] = tf32u(r3 - h3);
            }
            #pragma unroll
            for (int ni = 0; ni < 4; ni++) {
                const int n = cn + ni * 8 + g;
                unsigned b0 = tf32u(Wb[(kc + qd    ) * WS2 + n]);
                unsigned b1 = tf32u(Wb[(kc + qd + 4) * WS2 + n]);
                #pragma unroll
                for (int mi = 0; mi < 2; mi++) {
                    mma_tf32(acc[mi][ni], ah[mi][0], ah[mi][1], ah[mi][2], ah[mi][3], b0, b1);
                    mma_tf32(acc[mi][ni], al[mi][0], al[mi][1], al[mi][2], al[mi][3], b0, b1);
                }
            }
        }
        __syncthreads();
    }

    #pragma unroll
    for (int mi = 0; mi < 2; mi++) {
        const int mrow = m0 + rm + mi * 16 + g;
        const size_t r0 = (size_t)mrow * N;
        const size_t r1 = r0 + (size_t)8 * N;
        #pragma unroll
        for (int ni = 0; ni < 4; ni++) {
            const int col = n0 + cn + ni * 8 + 2 * qd;
            if (MODE == 1) {
                #pragma unroll
                for (int c2 = 0; c2 < 2; c2++) {
                    const int c = col + c2;
                    const int d = c & 31;
                    if (c < HID) {
                        // K: tf32-round + permK into C (g_kv)
                        const int pc = (c & ~31) | permK(d);
                        C[r0 + pc] = tf32r(acc[mi][ni][0 + c2]);
                        C[r1 + pc] = tf32r(acc[mi][ni][2 + c2]);
                    } else {
                        // V: fp16 transposed [b][h][d][s] into vt
                        const int h = (c - HID) >> 5;
                        const int b  = mrow >> 12;          // S_LEN = 4096
                        const int s  = mrow & (S_LEN - 1);
                        const size_t base = ((size_t)(b * HEADS + h) * DHEAD + d) * S_LEN;
                        vt[base + s]     = __float2half(acc[mi][ni][0 + c2]);
                        vt[base + s + 8] = __float2half(acc[mi][ni][2 + c2]);
                    }
                }
            } else {
                float b0v = 0.f, b1v = 0.f;
                if (MODE == 2) { b0v = bias[col]; b1v = bias[col + 1]; }
                *(float2*)&C[r0 + col] = make_float2(acc[mi][ni][0] + b0v, acc[mi][ni][1] + b1v);
                *(float2*)&C[r1 + col] = make_float2(acc[mi][ni][2] + b0v, acc[mi][ni][3] + b1v);
            }
        }
    }
}

// ---------------- tensor-core flash attention ----------------
// grid (T/64, H, B), block 128 (4 warps, 16 q-rows each). BN=64, cp.async x2.
// QK in tf32 (2-term Q split, K pre-rounded+permK). PV in fp16, P stays in registers
// (C-frag of S == A-frag of fp16 m16n8k16), V fp16 transposed [d][s] in smem.
#define QS 36
#define KS 36
#define VTS 72            // half stride for Vt rows (32 rows x 72 halves)
#define K_BUF (64 * KS)                 // floats
#define VT_BUF (32 * VTS)               // halves

__global__ void __launch_bounds__(128, 5)
attn_tc_kernel(const float* __restrict__ q,
               const float* __restrict__ kv,
               const __half* __restrict__ vt,
               float* __restrict__ ao) {
    extern __shared__ char smraw[];
    float*  Ksh = (float*)smraw;                              // 2 * 64*36 floats
    __half* Vsh = (__half*)(smraw + 2 * K_BUF * 4);           // 2 * 32*72 halves
    float*  Qst = (float*)(smraw + 2 * K_BUF * 4 + 2 * VT_BUF * 2);  // 64*36 floats

    const int b    = blockIdx.z;
    const int h    = blockIdx.y;
    const int t0   = blockIdx.x * 64;
    const int tid  = threadIdx.x;
    const int warp = tid >> 5;
    const int lane = tid & 31;
    const int g    = lane >> 2;
    const int qd   = lane & 3;
    const int prow = warp * 16 + g;

    const float*  kbase  = kv + ((size_t)b * S_LEN) * (2 * HID) + h * DHEAD;
    const __half* vtbase = vt + ((size_t)(b * HEADS + h) * DHEAD) * S_LEN;
    const int lrow = tid >> 3, lseg = (tid & 7) * 4;   // K loads: 16 rows/pass
    const int vrow = tid >> 2, vseg = (tid & 3);       // Vt loads: 32 rows, 8 halves/seg

    // ---- stage Q (raw fp32) into Qst, hoist fragments with QSCALE + hi/lo split
    {
        const float* qbase = q + ((size_t)(b * T_LEN + t0)) * HID + h * DHEAD;
        #pragma unroll
        for (int p = 0; p < 4; p++) {
            int r = p * 16 + lrow;
            cp16(&Qst[r * QS + lseg], &qbase[(size_t)r * HID + lseg]);
        }
        CP_COMMIT();
        CP_WAIT(0);
        __syncthreads();
    }

    unsigned qh[4][4], ql[4][4];
    #pragma unroll
    for (int ks = 0; ks < 4; ks++) {
        const int kc = ks * 8;
        float r0 = Qst[(prow    ) * QS + kc + qd    ] * QSCALE;
        float r1 = Qst[(prow + 8) * QS + kc + qd    ] * QSCALE;
        float r2 = Qst[(prow    ) * QS + kc + qd + 4] * QSCALE;
        float r3 = Qst[(prow + 8) * QS + kc + qd + 4] * QSCALE;
        float h0 = tf32r(r0), h1 = tf32r(r1), h2 = tf32r(r2), h3 = tf32r(r3);
        qh[ks][0] = __float_as_uint(h0); ql[ks][0] = tf32u(r0 - h0);
        qh[ks][1] = __float_as_uint(h1); ql[ks][1] = tf32u(r1 - h1);
        qh[ks][2] = __float_as_uint(h2); ql[ks][2] = tf32u(r2 - h2);
        qh[ks][3] = __float_as_uint(h3); ql[ks][3] = tf32u(r3 - h3);
    }

    float m0 = -1e30f, m1 = -1e30f;
    float l0 = 0.f,    l1 = 0.f;
    float O[4][4];
    #pragma unroll
    for (int j = 0; j < 4; j++)
        #pragma unroll
        for (int i = 0; i < 4; i++) O[j][i] = 0.f;

    auto load_kv = [&](int buf, int s0) {
        float*  Kb = Ksh + buf * K_BUF;
        __half* Vb = Vsh + buf * VT_BUF;
        #pragma unroll
        for (int p = 0; p < 4; p++) {
            int r = p * 16 + lrow;
            cp16(&Kb[r * KS + lseg], kbase + (size_t)(s0 + r) * (2 * HID) + lseg);
        }
        // Vt: 32 rows (d) x 64 halves (s). 2 cp16 per thread.
        #pragma unroll
        for (int p = 0; p < 2; p++) {
            int seg = vseg + p * 4;
            cp16(&Vb[vrow * VTS + seg * 8], vtbase + (size_t)vrow * S_LEN + s0 + seg * 8);
        }
    };

    const int n_chunks = S_LEN / 64;
    load_kv(0, 0);
    CP_COMMIT();

    for (int it = 0; it < n_chunks; it++) {
        if (it + 1 < n_chunks) {
            load_kv((it + 1) & 1, (it + 1) * 64);
            CP_COMMIT();
            CP_WAIT(1);
        } else {
            CP_WAIT(0);
        }
        __syncthreads();

        const float*  Kb = Ksh + (it & 1) * K_BUF;
        const __half* Vb = Vsh + (it & 1) * VT_BUF;

        // ---- S(log2) = Q @ K^T : K frags via LDS.64 (permK layout)
        float sacc[8][4];
        #pragma unroll
        for (int j = 0; j < 8; j++)
            #pragma unroll
            for (int i = 0; i < 4; i++) sacc[j][i] = 0.f;

        #pragma unroll
        for (int ks = 0; ks < 4; ks++) {
            const int kc = ks * 8;
            #pragma unroll
            for (int j = 0; j < 8; j++) {
                const int nr = j * 8 + g;
                float2 kf = *(const float2*)&Kb[nr * KS + kc + 2 * qd];
                unsigned b0 = __float_as_uint(kf.x);
                unsigned b1 = __float_as_uint(kf.y);
                mma_tf32(sacc[j], qh[ks][0], qh[ks][1], qh[ks][2], qh[ks][3], b0, b1);
                mma_tf32(sacc[j], ql[ks][0], ql[ks][1], ql[ks][2], ql[ks][3], b0, b1);
            }
        }

        // ---- online softmax (exp2 domain)
        float mx0 = -1e30f, mx1 = -1e30f;
        #pragma unroll
        for (int j = 0; j < 8; j++) {
            mx0 = fmaxf(mx0, fmaxf(sacc[j][0], sacc[j][1]));
            mx1 = fmaxf(mx1, fmaxf(sacc[j][2], sacc[j][3]));
        }
        #pragma unroll
        for (int off = 1; off < 4; off <<= 1) {
            mx0 = fmaxf(mx0, __shfl_xor_sync(0xffffffffu, mx0, off));
            mx1 = fmaxf(mx1, __shfl_xor_sync(0xffffffffu, mx1, off));
        }
        const float mn0 = fmaxf(m0, mx0);
        const float mn1 = fmaxf(m1, mx1);
        const float c0  = exp2f(m0 - mn0);
        const float c1  = exp2f(m1 - mn1);
        m0 = mn0; m1 = mn1;

        float ls0 = 0.f, ls1 = 0.f;
        #pragma unroll
        for (int j = 0; j < 8; j++) {
            sacc[j][0] = exp2f(sacc[j][0] - mn0);
            sacc[j][1] = exp2f(sacc[j][1] - mn0);
            sacc[j][2] = exp2f(sacc[j][2] - mn1);
            sacc[j][3] = exp2f(sacc[j][3] - mn1);
            ls0 += sacc[j][0] + sacc[j][1];
            ls1 += sacc[j][2] + sacc[j][3];
        }
        #pragma unroll
        for (int off = 1; off < 4; off <<= 1) {
            ls0 += __shfl_xor_sync(0xffffffffu, ls0, off);
            ls1 += __shfl_xor_sync(0xffffffffu, ls1, off);
        }
        l0 = l0 * c0 + ls0;
        l1 = l1 * c1 + ls1;
        #pragma unroll
        for (int j = 0; j < 4; j++) {
            O[j][0] *= c0; O[j][1] *= c0;
            O[j][2] *= c1; O[j][3] *= c1;
        }

        // ---- O += P @ V : P packs from registers (C-frag == A-frag), V fp16 [d][s]
        #pragma unroll
        for (int kb = 0; kb < 4; kb++) {
            unsigned a0 = packh2(sacc[2*kb    ][0], sacc[2*kb    ][1]);
            unsigned a1 = packh2(sacc[2*kb    ][2], sacc[2*kb    ][3]);
            unsigned a2 = packh2(sacc[2*kb + 1][0], sacc[2*kb + 1][1]);
            unsigned a3 = packh2(sacc[2*kb + 1][2], sacc[2*kb + 1][3]);
            const int sc = kb * 16 + 2 * qd;
            #pragma unroll
            for (int j = 0; j < 4; j++) {
                const __half* vr = Vb + (j * 8 + g) * VTS;
                unsigned b0 = *(const unsigned*)&vr[sc];
                unsigned b1 = *(const unsigned*)&vr[sc + 8];
                mma_f16(O[j], a0, a1, a2, a3, b0, b1);
            }
        }
        __syncthreads();
    }

    const float inv0 = 1.f / l0;
    const float inv1 = 1.f / l1;
    const size_t row0 = (size_t)(b * T_LEN + t0 + prow) * HID + h * DHEAD;
    const size_t row1 = row0 + (size_t)8 * HID;
    #pragma unroll
    for (int j = 0; j < 4; j++) {
        const int d0 = j * 8 + 2 * qd;
        *(float2*)&ao[row0 + d0] = make_float2(O[j][0] * inv0, O[j][1] * inv0);
        *(float2*)&ao[row1 + d0] = make_float2(O[j][2] * inv1, O[j][3] * inv1);
    }
}

// ---------------- launch ----------------
extern "C" void kernel_launch(void* const* d_in, const int* in_sizes, int n_in,
                              void* d_out, int out_size) {
    const float* x    = (const float*)d_in[0];
    const float* ctx  = (const float*)d_in[1];
    const float* w_q  = (const float*)d_in[2];
    const float* w_kv = (const float*)d_in[3];
    const float* w_o  = (const float*)d_in[4];
    const float* b_o  = (const float*)d_in[5];
    float* out = (float*)d_out;

    float*  q  = nullptr; cudaGetSymbolAddress((void**)&q,  g_q);
    float*  kv = nullptr; cudaGetSymbolAddress((void**)&kv, g_kv);
    __half* vt = nullptr; cudaGetSymbolAddress((void**)&vt, g_vt);
    float*  ao = nullptr; cudaGetSymbolAddress((void**)&ao, g_ao);

    const int MQ = B_SZ * T_LEN;   // 8192
    const int MK = B_SZ * S_LEN;   // 16384

    const int gemm_smem = (2 * A_BUF + 2 * W_BUF) * sizeof(float);
    const int attn_smem = 2 * K_BUF * 4 + 2 * VT_BUF * 2 + 64 * QS * 4;   // ~36.9 KB

    cudaFuncSetAttribute(gemm_tc_kernel<0>,
                         cudaFuncAttributeMaxDynamicSharedMemorySize, gemm_smem);
    cudaFuncSetAttribute(gemm_tc_kernel<1>,
                         cudaFuncAttributeMaxDynamicSharedMemorySize, gemm_smem);
    cudaFuncSetAttribute(gemm_tc_kernel<2>,
                         cudaFuncAttributeMaxDynamicSharedMemorySize, gemm_smem);
    cudaFuncSetAttribute(attn_tc_kernel,
                         cudaFuncAttributeMaxDynamicSharedMemorySize, attn_smem);

    gemm_tc_kernel<0><<<dim3(HID / 64, MQ / 128), 256, gemm_smem>>>(x, w_q, nullptr, q, nullptr, MQ, HID, DIM);
    gemm_tc_kernel<1><<<dim3(2 * HID / 64, MK / 128), 256, gemm_smem>>>(ctx, w_kv, nullptr, kv, vt, MK, 2 * HID, DIM);
    attn_tc_kernel<<<dim3(T_LEN / 64, HEADS, B_SZ), 128, attn_smem>>>(q, kv, vt, ao);
    gemm_tc_kernel<2><<<dim3(DIM / 64, MQ / 128), 256, gemm_smem>>>(ao, w_o, b_o, out, nullptr, MQ, DIM, HID);
}

// round 10
// speedup vs baseline: 10.5156x; 1.3788x over previous
#include <cuda_runtime.h>
#include <cuda_bf16.h>
#include <cuda_fp16.h>
#include <math.h>

#define B_SZ   4
#define T_LEN  2048
#define S_LEN  4096
#define DIM    256
#define HEADS  8
#define DHEAD  32
#define HID    256
#define SCALE  0.17677669529663687f   // 32^-0.5
#define QSCALE 0.25505567633920995f   // SCALE * log2(e)

// ---------------- scratch (no allocation allowed) ----------------
__device__ float  g_q [B_SZ * T_LEN * HID];
__device__ __half g_kh[B_SZ * HEADS * S_LEN * DHEAD];   // K fp16, permuted cols, [b][h][s][32]
__device__ __half g_vt[B_SZ * HEADS * DHEAD * S_LEN];   // V fp16, transposed [b][h][d][s]
__device__ float  g_ao[B_SZ * T_LEN * HID];

// ---------------- helpers ----------------
__device__ __forceinline__ float tf32r(float x) {
    unsigned int u;
    asm("cvt.rna.tf32.f32 %0, %1;" : "=r"(u) : "f"(x));
    return __uint_as_float(u);
}
__device__ __forceinline__ unsigned tf32u(float x) {
    unsigned int u;
    asm("cvt.rna.tf32.f32 %0, %1;" : "=r"(u) : "f"(x));
    return u;
}
__device__ __forceinline__ unsigned packh2(float lo, float hi) {
    __half2 h = __floats2half2_rn(lo, hi);
    return *(unsigned*)&h;
}

__device__ __forceinline__ void mma_tf32(float* c,
                                         unsigned a0, unsigned a1, unsigned a2, unsigned a3,
                                         unsigned b0, unsigned b1) {
    asm volatile(
        "mma.sync.aligned.m16n8k8.row.col.f32.tf32.tf32.f32 "
        "{%0,%1,%2,%3}, {%4,%5,%6,%7}, {%8,%9}, {%0,%1,%2,%3};"
        : "+f"(c[0]), "+f"(c[1]), "+f"(c[2]), "+f"(c[3])
        : "r"(a0), "r"(a1), "r"(a2), "r"(a3), "r"(b0), "r"(b1));
}
__device__ __forceinline__ void mma_f16(float* c,
                                        unsigned a0, unsigned a1, unsigned a2, unsigned a3,
                                        unsigned b0, unsigned b1) {
    asm volatile(
        "mma.sync.aligned.m16n8k16.row.col.f32.f16.f16.f32 "
        "{%0,%1,%2,%3}, {%4,%5,%6,%7}, {%8,%9}, {%0,%1,%2,%3};"
        : "+f"(c[0]), "+f"(c[1]), "+f"(c[2]), "+f"(c[3])
        : "r"(a0), "r"(a1), "r"(a2), "r"(a3), "r"(b0), "r"(b1));
}

__device__ __forceinline__ void cp16(void* smem_ptr, const void* gmem_ptr) {
    unsigned s = (unsigned)__cvta_generic_to_shared(smem_ptr);
    asm volatile("cp.async.cg.shared.global [%0], [%1], 16;" :: "r"(s), "l"(gmem_ptr));
}
#define CP_COMMIT() asm volatile("cp.async.commit_group;")
#define CP_WAIT(n)  asm volatile("cp.async.wait_group %0;" :: "n"(n))

// K column permutation for fp16 m16n8k16 B-frags:
// within each 16-d block, logical d -> position qd*4 + hi8*2 + (d&1),
// so thread qd reads its 4 halves {2qd,2qd+1,2qd+8,2qd+9} as one 8-byte load.
__device__ __forceinline__ int permK16(int d) {
    const int kb = d >> 4, dl = d & 15;
    return kb * 16 + ((dl & 7) >> 1) * 4 + ((dl >> 3) << 1) + (dl & 1);
}

// ---------------- tf32 GEMM, cp.async double-buffered ----------------
// MODE: 0 = plain fp32 store, 1 = KV store (K fp16+permK16 -> kh; V fp16 transposed -> vt), 2 = +bias
#define AS2 36
#define WS2 72
#define A_BUF (128 * AS2)
#define W_BUF (32 * WS2)

template<int MODE>
__global__ void gemm_tc_kernel(const float* __restrict__ A,
                               const float* __restrict__ W,
                               const float* __restrict__ bias,
                               float* __restrict__ C,
                               __half* __restrict__ kh,
                               __half* __restrict__ vt,
                               int M, int N, int K) {
    extern __shared__ float sg[];
    float* Asm = sg;
    float* Wsm = sg + 2 * A_BUF;

    const int tid  = threadIdx.x;
    const int warp = tid >> 5;
    const int lane = tid & 31;
    const int g    = lane >> 2;
    const int qd   = lane & 3;
    const int m0 = blockIdx.y * 128;
    const int n0 = blockIdx.x * 64;
    const int rm = (warp & 3) * 32;
    const int cn = (warp >> 2) * 32;

    const int a_row = tid >> 3, a_seg = (tid & 7) * 4;
    const int w_row = tid >> 4, w_seg = (tid & 15) * 4;

    float acc[2][4][4];
    #pragma unroll
    for (int mi = 0; mi < 2; mi++)
        #pragma unroll
        for (int ni = 0; ni < 4; ni++)
            #pragma unroll
            for (int i = 0; i < 4; i++) acc[mi][ni][i] = 0.f;

    auto load_tiles = [&](int buf, int k0) {
        float* Ab = Asm + buf * A_BUF;
        float* Wb = Wsm + buf * W_BUF;
        #pragma unroll
        for (int p = 0; p < 4; p++) {
            int r = p * 32 + a_row;
            cp16(&Ab[r * AS2 + a_seg], &A[(size_t)(m0 + r) * K + k0 + a_seg]);
        }
        #pragma unroll
        for (int p = 0; p < 2; p++) {
            int r = p * 16 + w_row;
            cp16(&Wb[r * WS2 + w_seg], &W[(size_t)(k0 + r) * N + n0 + w_seg]);
        }
    };

    const int n_iter = K / 32;
    load_tiles(0, 0);
    CP_COMMIT();

    for (int it = 0; it < n_iter; it++) {
        if (it + 1 < n_iter) {
            load_tiles((it + 1) & 1, (it + 1) * 32);
            CP_COMMIT();
            CP_WAIT(1);
        } else {
            CP_WAIT(0);
        }
        __syncthreads();

        const float* Ab = Asm + (it & 1) * A_BUF;
        const float* Wb = Wsm + (it & 1) * W_BUF;

        #pragma unroll
        for (int ks = 0; ks < 4; ks++) {
            const int kc = ks * 8;
            unsigned ah[2][4], al[2][4];
            #pragma unroll
            for (int mi = 0; mi < 2; mi++) {
                const int r = rm + mi * 16 + g;
                float r0 = Ab[(r    ) * AS2 + kc + qd    ];
                float r1 = Ab[(r + 8) * AS2 + kc + qd    ];
                float r2 = Ab[(r    ) * AS2 + kc + qd + 4];
                float r3 = Ab[(r + 8) * AS2 + kc + qd + 4];
                float h0 = tf32r(r0), h1 = tf32r(r1), h2 = tf32r(r2), h3 = tf32r(r3);
                ah[mi][0] = __float_as_uint(h0); al[mi][0] = tf32u(r0 - h0);
                ah[mi][1] = __float_as_uint(h1); al[mi][1] = tf32u(r1 - h1);
                ah[mi][2] = __float_as_uint(h2); al[mi][2] = tf32u(r2 - h2);
                ah[mi][3] = __float_as_uint(h3); al[mi][3] = tf32u(r3 - h3);
            }
            #pragma unroll
            for (int ni = 0; ni < 4; ni++) {
                const int n = cn + ni * 8 + g;
                unsigned b0 = tf32u(Wb[(kc + qd    ) * WS2 + n]);
                unsigned b1 = tf32u(Wb[(kc + qd + 4) * WS2 + n]);
                #pragma unroll
                for (int mi = 0; mi < 2; mi++) {
                    mma_tf32(acc[mi][ni], ah[mi][0], ah[mi][1], ah[mi][2], ah[mi][3], b0, b1);
                    mma_tf32(acc[mi][ni], al[mi][0], al[mi][1], al[mi][2], al[mi][3], b0, b1);
                }
            }
        }
        __syncthreads();
    }

    #pragma unroll
    for (int mi = 0; mi < 2; mi++) {
        const int mrow = m0 + rm + mi * 16 + g;
        const size_t r0 = (size_t)mrow * N;
        const size_t r1 = r0 + (size_t)8 * N;
        #pragma unroll
        for (int ni = 0; ni < 4; ni++) {
            const int col = n0 + cn + ni * 8 + 2 * qd;
            if (MODE == 1) {
                const int bb = mrow >> 12;              // S_LEN = 4096
                const int s  = mrow & (S_LEN - 1);
                #pragma unroll
                for (int c2 = 0; c2 < 2; c2++) {
                    const int c = col + c2;
                    const int d = c & 31;
                    if (c < HID) {
                        // K: fp16 + permK16 into kh [b][h][s][32]
                        const int h = c >> 5;
                        const size_t base =
                            ((size_t)(bb * HEADS + h) * S_LEN + s) * DHEAD + permK16(d);
                        kh[base]             = __float2half(acc[mi][ni][0 + c2]);
                        kh[base + 8 * DHEAD] = __float2half(acc[mi][ni][2 + c2]);
                    } else {
                        // V: fp16 transposed [b][h][d][s] into vt
                        const int h = (c - HID) >> 5;
                        const size_t base = ((size_t)(bb * HEADS + h) * DHEAD + d) * S_LEN;
                        vt[base + s]     = __float2half(acc[mi][ni][0 + c2]);
                        vt[base + s + 8] = __float2half(acc[mi][ni][2 + c2]);
                    }
                }
            } else {
                float b0v = 0.f, b1v = 0.f;
                if (MODE == 2) { b0v = bias[col]; b1v = bias[col + 1]; }
                *(float2*)&C[r0 + col] = make_float2(acc[mi][ni][0] + b0v, acc[mi][ni][1] + b1v);
                *(float2*)&C[r1 + col] = make_float2(acc[mi][ni][2] + b0v, acc[mi][ni][3] + b1v);
            }
        }
    }
}

// ---------------- tensor-core flash attention (all-fp16 MMA) ----------------
// grid (T/64, H, B), block 128 (4 warps, 16 q-rows each). BN=64, cp.async x2.
// QK: fp16 m16n8k16, 2-term Q hi/lo split, K fp16 pre-permuted.
// PV: fp16 m16n8k16, P direct from registers, V fp16 transposed [d][s].
#define QS 36
#define KS16 48           // halves per K smem row (96 B, conflict-free, 16B-aligned)
#define VTS 72            // halves per Vt smem row
#define K_BUF16 (64 * KS16)             // halves
#define VT_BUF  (32 * VTS)              // halves

__global__ void __launch_bounds__(128, 5)
attn_tc_kernel(const float* __restrict__ q,
               const __half* __restrict__ kh,
               const __half* __restrict__ vt,
               float* __restrict__ ao) {
    extern __shared__ char smraw[];
    __half* Ksh = (__half*)smraw;                              // 2 * 64*48 halves
    __half* Vsh = (__half*)(smraw + 2 * K_BUF16 * 2);          // 2 * 32*72 halves
    float*  Qst = (float*)(smraw + 2 * K_BUF16 * 2 + 2 * VT_BUF * 2);  // 64*36 floats

    const int b    = blockIdx.z;
    const int h    = blockIdx.y;
    const int t0   = blockIdx.x * 64;
    const int tid  = threadIdx.x;
    const int warp = tid >> 5;
    const int lane = tid & 31;
    const int g    = lane >> 2;
    const int qd   = lane & 3;
    const int prow = warp * 16 + g;

    const __half* khbase = kh + ((size_t)(b * HEADS + h) * S_LEN) * DHEAD;
    const __half* vtbase = vt + ((size_t)(b * HEADS + h) * DHEAD) * S_LEN;
    const int lrow = tid >> 3, lseg = (tid & 7) * 4;   // Q stage: 16 rows/pass
    const int krow = tid >> 2, kseg = (tid & 3);       // K loads: 32 rows/pass, 8 halves/seg
    const int vrow = tid >> 2, vseg = (tid & 3);       // Vt loads

    // ---- stage Q (raw fp32), then build fp16 hi/lo A-frags with QSCALE folded in
    {
        const float* qbase = q + ((size_t)(b * T_LEN + t0)) * HID + h * DHEAD;
        #pragma unroll
        for (int p = 0; p < 4; p++) {
            int r = p * 16 + lrow;
            cp16(&Qst[r * QS + lseg], &qbase[(size_t)r * HID + lseg]);
        }
        CP_COMMIT();
        CP_WAIT(0);
        __syncthreads();
    }

    unsigned qh[2][4], ql[2][4];
    #pragma unroll
    for (int ks = 0; ks < 2; ks++) {
        const int kb = ks * 16;
        // a0: row prow  k {2qd,2qd+1}; a1: row prow+8 same k;
        // a2: row prow  k {2qd+8,2qd+9}; a3: row prow+8 same.
        float2 x0 = *(const float2*)&Qst[(prow    ) * QS + kb + 2 * qd    ];
        float2 x1 = *(const float2*)&Qst[(prow + 8) * QS + kb + 2 * qd    ];
        float2 x2 = *(const float2*)&Qst[(prow    ) * QS + kb + 2 * qd + 8];
        float2 x3 = *(const float2*)&Qst[(prow + 8) * QS + kb + 2 * qd + 8];
        float2 xs[4] = {x0, x1, x2, x3};
        #pragma unroll
        for (int i = 0; i < 4; i++) {
            float ax = xs[i].x * QSCALE, ay = xs[i].y * QSCALE;
            __half hx = __float2half(ax), hy = __float2half(ay);
            __half2 H = __halves2half2(hx, hy);
            qh[ks][i] = *(unsigned*)&H;
            ql[ks][i] = packh2(ax - __half2float(hx), ay - __half2float(hy));
        }
    }

    float m0 = -1e30f, m1 = -1e30f;
    float l0 = 0.f,    l1 = 0.f;
    float O[4][4];
    #pragma unroll
    for (int j = 0; j < 4; j++)
        #pragma unroll
        for (int i = 0; i < 4; i++) O[j][i] = 0.f;

    auto load_kv = [&](int buf, int s0) {
        __half* Kb = Ksh + buf * K_BUF16;
        __half* Vb = Vsh + buf * VT_BUF;
        #pragma unroll
        for (int p = 0; p < 2; p++) {
            int r = p * 32 + krow;
            cp16(&Kb[r * KS16 + kseg * 8], khbase + (size_t)(s0 + r) * DHEAD + kseg * 8);
        }
        #pragma unroll
        for (int p = 0; p < 2; p++) {
            int seg = vseg + p * 4;
            cp16(&Vb[vrow * VTS + seg * 8], vtbase + (size_t)vrow * S_LEN + s0 + seg * 8);
        }
    };

    const int n_chunks = S_LEN / 64;
    load_kv(0, 0);
    CP_COMMIT();

    for (int it = 0; it < n_chunks; it++) {
        if (it + 1 < n_chunks) {
            load_kv((it + 1) & 1, (it + 1) * 64);
            CP_COMMIT();
            CP_WAIT(1);
        } else {
            CP_WAIT(0);
        }
        __syncthreads();

        const __half* Kb = Ksh + (it & 1) * K_BUF16;
        const __half* Vb = Vsh + (it & 1) * VT_BUF;

        // ---- S(log2) = Q @ K^T : fp16 k16, K frags as one LDS.64 each
        float sacc[8][4];
        #pragma unroll
        for (int j = 0; j < 8; j++)
            #pragma unroll
            for (int i = 0; i < 4; i++) sacc[j][i] = 0.f;

        #pragma unroll
        for (int ks = 0; ks < 2; ks++) {
            const int ko = ks * 16 + qd * 4;
            #pragma unroll
            for (int j = 0; j < 8; j++) {
                uint2 kk = *(const uint2*)&Kb[(j * 8 + g) * KS16 + ko];
                mma_f16(sacc[j], qh[ks][0], qh[ks][1], qh[ks][2], qh[ks][3], kk.x, kk.y);
                mma_f16(sacc[j], ql[ks][0], ql[ks][1], ql[ks][2], ql[ks][3], kk.x, kk.y);
            }
        }

        // ---- online softmax (exp2 domain)
        float mx0 = -1e30f, mx1 = -1e30f;
        #pragma unroll
        for (int j = 0; j < 8; j++) {
            mx0 = fmaxf(mx0, fmaxf(sacc[j][0], sacc[j][1]));
            mx1 = fmaxf(mx1, fmaxf(sacc[j][2], sacc[j][3]));
        }
        #pragma unroll
        for (int off = 1; off < 4; off <<= 1) {
            mx0 = fmaxf(mx0, __shfl_xor_sync(0xffffffffu, mx0, off));
            mx1 = fmaxf(mx1, __shfl_xor_sync(0xffffffffu, mx1, off));
        }
        const float mn0 = fmaxf(m0, mx0);
        const float mn1 = fmaxf(m1, mx1);
        const float c0  = exp2f(m0 - mn0);
        const float c1  = exp2f(m1 - mn1);
        m0 = mn0; m1 = mn1;

        float ls0 = 0.f, ls1 = 0.f;
        #pragma unroll
        for (int j = 0; j < 8; j++) {
            sacc[j][0] = exp2f(sacc[j][0] - mn0);
            sacc[j][1] = exp2f(sacc[j][1] - mn0);
            sacc[j][2] = exp2f(sacc[j][2] - mn1);
            sacc[j][3] = exp2f(sacc[j][3] - mn1);
            ls0 += sacc[j][0] + sacc[j][1];
            ls1 += sacc[j][2] + sacc[j][3];
        }
        #pragma unroll
        for (int off = 1; off < 4; off <<= 1) {
            ls0 += __shfl_xor_sync(0xffffffffu, ls0, off);
            ls1 += __shfl_xor_sync(0xffffffffu, ls1, off);
        }
        l0 = l0 * c0 + ls0;
        l1 = l1 * c1 + ls1;
        #pragma unroll
        for (int j = 0; j < 4; j++) {
            O[j][0] *= c0; O[j][1] *= c0;
            O[j][2] *= c1; O[j][3] *= c1;
        }

        // ---- O += P @ V : P packs from registers (C-frag == A-frag), V fp16 [d][s]
        #pragma unroll
        for (int kb = 0; kb < 4; kb++) {
            unsigned a0 = packh2(sacc[2*kb    ][0], sacc[2*kb    ][1]);
            unsigned a1 = packh2(sacc[2*kb    ][2], sacc[2*kb    ][3]);
            unsigned a2 = packh2(sacc[2*kb + 1][0], sacc[2*kb + 1][1]);
            unsigned a3 = packh2(sacc[2*kb + 1][2], sacc[2*kb + 1][3]);
            const int sc = kb * 16 + 2 * qd;
            #pragma unroll
            for (int j = 0; j < 4; j++) {
                const __half* vr = Vb + (j * 8 + g) * VTS;
                unsigned b0 = *(const unsigned*)&vr[sc];
                unsigned b1 = *(const unsigned*)&vr[sc + 8];
                mma_f16(O[j], a0, a1, a2, a3, b0, b1);
            }
        }
        __syncthreads();
    }

    const float inv0 = 1.f / l0;
    const float inv1 = 1.f / l1;
    const size_t row0 = (size_t)(b * T_LEN + t0 + prow) * HID + h * DHEAD;
    const size_t row1 = row0 + (size_t)8 * HID;
    #pragma unroll
    for (int j = 0; j < 4; j++) {
        const int d0 = j * 8 + 2 * qd;
        *(float2*)&ao[row0 + d0] = make_float2(O[j][0] * inv0, O[j][1] * inv0);
        *(float2*)&ao[row1 + d0] = make_float2(O[j][2] * inv1, O[j][3] * inv1);
    }
}

// ---------------- launch ----------------
extern "C" void kernel_launch(void* const* d_in, const int* in_sizes, int n_in,
                              void* d_out, int out_size) {
    const float* x    = (const float*)d_in[0];
    const float* ctx  = (const float*)d_in[1];
    const float* w_q  = (const float*)d_in[2];
    const float* w_kv = (const float*)d_in[3];
    const float* w_o  = (const float*)d_in[4];
    const float* b_o  = (const float*)d_in[5];
    float* out = (float*)d_out;

    float*  q  = nullptr; cudaGetSymbolAddress((void**)&q,  g_q);
    __half* kh = nullptr; cudaGetSymbolAddress((void**)&kh, g_kh);
    __half* vt = nullptr; cudaGetSymbolAddress((void**)&vt, g_vt);
    float*  ao = nullptr; cudaGetSymbolAddress((void**)&ao, g_ao);

    const int MQ = B_SZ * T_LEN;   // 8192
    const int MK = B_SZ * S_LEN;   // 16384

    const int gemm_smem = (2 * A_BUF + 2 * W_BUF) * sizeof(float);
    const int attn_smem = 2 * K_BUF16 * 2 + 2 * VT_BUF * 2 + 64 * QS * 4;   // 30720 B

    cudaFuncSetAttribute(gemm_tc_kernel<0>,
                         cudaFuncAttributeMaxDynamicSharedMemorySize, gemm_smem);
    cudaFuncSetAttribute(gemm_tc_kernel<1>,
                         cudaFuncAttributeMaxDynamicSharedMemorySize, gemm_smem);
    cudaFuncSetAttribute(gemm_tc_kernel<2>,
                         cudaFuncAttributeMaxDynamicSharedMemorySize, gemm_smem);
    cudaFuncSetAttribute(attn_tc_kernel,
                         cudaFuncAttributeMaxDynamicSharedMemorySize, attn_smem);

    gemm_tc_kernel<0><<<dim3(HID / 64, MQ / 128), 256, gemm_smem>>>(x, w_q, nullptr, q, nullptr, nullptr, MQ, HID, DIM);
    gemm_tc_kernel<1><<<dim3(2 * HID / 64, MK / 128), 256, gemm_smem>>>(ctx, w_kv, nullptr, nullptr, kh, vt, MK, 2 * HID, DIM);
    attn_tc_kernel<<<dim3(T_LEN / 64, HEADS, B_SZ), 128, attn_smem>>>(q, kh, vt, ao);
    gemm_tc_kernel<2><<<dim3(DIM / 64, MQ / 128), 256, gemm_smem>>>(ao, w_o, b_o, out, nullptr, nullptr, MQ, DIM, HID);
}